// round 1
// baseline (speedup 1.0000x reference)
#include <cuda_runtime.h>

// Problem constants (shapes fixed by the dataset)
#define TOK   25088      // B*N = 128*196
#define CDIM  768
#define NQKV  2304
#define HEADS 12
#define EDIM  64
#define NBH   96         // b*h = 8*12
#define SDIM  3136       // num_frames*N = 16*196
#define NFRM  16
#define BATB  8          // B/num_frames
#define EPSV  1e-4f

// Scratch (allocation-free rule: __device__ globals)
__device__ float g_q   [(size_t)TOK * CDIM];
__device__ float g_k   [(size_t)TOK * CDIM];
__device__ float g_v   [(size_t)TOK * CDIM];
__device__ float g_attn[(size_t)TOK * CDIM];
__device__ float g_kv  [NBH * EDIM * EDIM];
__device__ float g_ksum[NBH * EDIM];

// ---------------------------------------------------------------------------
// TN sgemm: C[m,n] = sum_k A[m,k] * B[n,k]   (both row-major, K-contiguous)
// 128x128 block tile, BK=8, 256 threads, 8x8 per-thread micro-tile.
// mode 0: qkv epilogue -> split into g_q/g_k/g_v with relu on q,k
// mode 1: proj epilogue -> A is g_attn, add bias, write Cout
// ---------------------------------------------------------------------------
__global__ __launch_bounds__(256, 2) void sgemm_tn(
    const float* __restrict__ A, const float* __restrict__ B,
    const float* __restrict__ bias, float* __restrict__ Cout,
    int K, int mode)
{
    __shared__ float As[8][128];
    __shared__ float Bs[8][128];

    const int tid = threadIdx.x;
    const int tx  = tid & 15;        // 0..15 -> 8 cols each
    const int ty  = tid >> 4;        // 0..15 -> 8 rows each
    const int bx  = blockIdx.x;      // N tile
    const int by  = blockIdx.y;      // M tile

    const int arow = tid >> 1;       // 0..127
    const int acol = (tid & 1) * 4;  // 0 or 4

    if (mode == 1) A = g_attn;       // device-side symbol reference

    const float* Ag = A + (size_t)(by * 128 + arow) * K + acol;
    const float* Bg = B + (size_t)(bx * 128 + arow) * K + acol;

    float acc[8][8];
    #pragma unroll
    for (int i = 0; i < 8; i++)
        #pragma unroll
        for (int j = 0; j < 8; j++) acc[i][j] = 0.0f;

    for (int k0 = 0; k0 < K; k0 += 8) {
        float4 av = *(const float4*)(Ag + k0);
        float4 bv = *(const float4*)(Bg + k0);
        As[acol + 0][arow] = av.x;
        As[acol + 1][arow] = av.y;
        As[acol + 2][arow] = av.z;
        As[acol + 3][arow] = av.w;
        Bs[acol + 0][arow] = bv.x;
        Bs[acol + 1][arow] = bv.y;
        Bs[acol + 2][arow] = bv.z;
        Bs[acol + 3][arow] = bv.w;
        __syncthreads();

        #pragma unroll
        for (int kk = 0; kk < 8; kk++) {
            float ra[8], rb[8];
            #pragma unroll
            for (int i = 0; i < 8; i++) ra[i] = As[kk][ty * 8 + i];
            #pragma unroll
            for (int j = 0; j < 8; j++) rb[j] = Bs[kk][tx * 8 + j];
            #pragma unroll
            for (int i = 0; i < 8; i++)
                #pragma unroll
                for (int j = 0; j < 8; j++)
                    acc[i][j] = fmaf(ra[i], rb[j], acc[i][j]);
        }
        __syncthreads();
    }

    const int r0 = by * 128 + ty * 8;
    if (mode == 0) {
        // cols [0,768)->q(relu), [768,1536)->k(relu), [1536,2304)->v
        const int which = (bx * 128) / CDIM;   // whole tile is in one segment
        const int cc0   = bx * 128 + tx * 8 - which * CDIM;
        float* dst = (which == 0) ? g_q : (which == 1) ? g_k : g_v;
        const bool dorelu = (which < 2);
        #pragma unroll
        for (int i = 0; i < 8; i++) {
            float* drow = dst + (size_t)(r0 + i) * CDIM + cc0;
            #pragma unroll
            for (int j = 0; j < 8; j++) {
                float val = acc[i][j];
                if (dorelu) val = fmaxf(val, 0.0f);
                drow[j] = val;
            }
        }
    } else {
        const int c0 = bx * 128 + tx * 8;
        float bv8[8];
        #pragma unroll
        for (int j = 0; j < 8; j++) bv8[j] = bias[c0 + j];
        #pragma unroll
        for (int i = 0; i < 8; i++) {
            float* drow = Cout + (size_t)(r0 + i) * CDIM + c0;
            #pragma unroll
            for (int j = 0; j < 8; j++)
                drow[j] = acc[i][j] + bv8[j];
        }
    }
}

// ---------------------------------------------------------------------------
// kv[b,h,e,d] = sum_s k[b,s,h,e]*v[b,s,h,d];  ksum[b,h,e] = sum_s k[b,s,h,e]
// one block per (b,h); 256 threads, 4x4 per-thread accumulators over 64x64.
// ---------------------------------------------------------------------------
__global__ __launch_bounds__(256) void kv_reduce()
{
    const int bh = blockIdx.x;          // 0..95
    const int b  = bh / HEADS;
    const int h  = bh % HEADS;
    const float* kbase = g_k + (size_t)b * SDIM * CDIM + h * EDIM;
    const float* vbase = g_v + (size_t)b * SDIM * CDIM + h * EDIM;

    __shared__ float ks[8][EDIM];
    __shared__ float vs[8][EDIM];

    const int tid = threadIdx.x;
    const int tx  = tid & 15;
    const int ty  = tid >> 4;

    float acc[4][4];
    #pragma unroll
    for (int i = 0; i < 4; i++)
        #pragma unroll
        for (int j = 0; j < 4; j++) acc[i][j] = 0.0f;
    float ksum = 0.0f;   // valid for tid < 64 (e = tid)

    for (int s0 = 0; s0 < SDIM; s0 += 8) {
        for (int i = tid; i < 8 * EDIM; i += 256) {
            const int sr = i >> 6, e = i & 63;
            ks[sr][e] = kbase[(size_t)(s0 + sr) * CDIM + e];
            vs[sr][e] = vbase[(size_t)(s0 + sr) * CDIM + e];
        }
        __syncthreads();
        #pragma unroll
        for (int sr = 0; sr < 8; sr++) {
            float rk[4], rv[4];
            #pragma unroll
            for (int i = 0; i < 4; i++) rk[i] = ks[sr][ty * 4 + i];
            #pragma unroll
            for (int j = 0; j < 4; j++) rv[j] = vs[sr][tx * 4 + j];
            #pragma unroll
            for (int i = 0; i < 4; i++)
                #pragma unroll
                for (int j = 0; j < 4; j++)
                    acc[i][j] = fmaf(rk[i], rv[j], acc[i][j]);
            if (tid < EDIM) ksum += ks[sr][tid];
        }
        __syncthreads();
    }

    float* kvout = g_kv + (size_t)bh * EDIM * EDIM;
    #pragma unroll
    for (int i = 0; i < 4; i++)
        #pragma unroll
        for (int j = 0; j < 4; j++)
            kvout[(ty * 4 + i) * EDIM + tx * 4 + j] = acc[i][j];
    if (tid < EDIM) g_ksum[bh * EDIM + tid] = ksum;
}

// ---------------------------------------------------------------------------
// out[b,s,h,d] = (sum_e q[b,s,h,e]*kv[b,h,e,d]) / (q.ksum + eps)
// block = (bh, s-tile of 64); writes g_attn in (token, C) layout.
// ---------------------------------------------------------------------------
__global__ __launch_bounds__(256) void attn_out()
{
    const int bh = blockIdx.x;   // 0..95
    const int st = blockIdx.y;   // 0..48
    const int b  = bh / HEADS;
    const int h  = bh % HEADS;

    __shared__ float kvs[EDIM][EDIM + 1];
    __shared__ float qs [EDIM][EDIM + 1];
    __shared__ float ksum_s[EDIM];
    __shared__ float zs[EDIM];

    const int tid = threadIdx.x;
    const int tx  = tid & 15;
    const int ty  = tid >> 4;

    const float* qbase  = g_q + (size_t)(b * SDIM + st * 64) * CDIM + h * EDIM;
    const float* kvbase = g_kv + (size_t)bh * EDIM * EDIM;

    for (int i = tid; i < EDIM * EDIM; i += 256) {
        const int r = i >> 6, c = i & 63;
        kvs[r][c] = kvbase[i];
        qs [r][c] = qbase[(size_t)r * CDIM + c];
    }
    if (tid < EDIM) ksum_s[tid] = g_ksum[bh * EDIM + tid];
    __syncthreads();

    if (tid < EDIM) {
        float d = 0.0f;
        #pragma unroll
        for (int e = 0; e < EDIM; e++) d = fmaf(qs[tid][e], ksum_s[e], d);
        zs[tid] = 1.0f / (d + EPSV);
    }
    __syncthreads();

    float acc[4][4];
    #pragma unroll
    for (int i = 0; i < 4; i++)
        #pragma unroll
        for (int j = 0; j < 4; j++) acc[i][j] = 0.0f;

    #pragma unroll 8
    for (int e = 0; e < EDIM; e++) {
        float rq[4], rkv[4];
        #pragma unroll
        for (int i = 0; i < 4; i++) rq[i] = qs[ty * 4 + i][e];
        #pragma unroll
        for (int j = 0; j < 4; j++) rkv[j] = kvs[e][tx * 4 + j];
        #pragma unroll
        for (int i = 0; i < 4; i++)
            #pragma unroll
            for (int j = 0; j < 4; j++)
                acc[i][j] = fmaf(rq[i], rkv[j], acc[i][j]);
    }

    #pragma unroll
    for (int i = 0; i < 4; i++) {
        const int s = ty * 4 + i;
        const size_t token = (size_t)(b * SDIM + st * 64 + s);
        float* drow = g_attn + token * CDIM + h * EDIM + tx * 4;
        const float z = zs[s];
        #pragma unroll
        for (int j = 0; j < 4; j++)
            drow[j] = acc[i][j] * z;
    }
}

// ---------------------------------------------------------------------------
extern "C" void kernel_launch(void* const* d_in, const int* in_sizes, int n_in,
                              void* d_out, int out_size)
{
    const float* x     = (const float*)d_in[0];   // (128,196,768)
    const float* Wqkv  = (const float*)d_in[1];   // (2304,768)
    const float* Wproj = (const float*)d_in[2];   // (768,768)
    const float* bproj = (const float*)d_in[3];   // (768,)
    float* out = (float*)d_out;

    // 1) qkv = x @ Wqkv^T, split + relu -> g_q, g_k, g_v
    sgemm_tn<<<dim3(NQKV / 128, TOK / 128), 256>>>(x, Wqkv, nullptr, nullptr, CDIM, 0);
    // 2) kv outer-product reduction + k_sum per (b,h)
    kv_reduce<<<NBH, 256>>>();
    // 3) normalized attention output -> g_attn
    attn_out<<<dim3(NBH, SDIM / 64), 256>>>();
    // 4) out = g_attn @ Wproj^T + b_proj
    sgemm_tn<<<dim3(CDIM / 128, TOK / 128), 256>>>(nullptr, Wproj, bproj, out, CDIM, 1);
}

// round 6
// speedup vs baseline: 2.0907x; 2.0907x over previous
#include <cuda_runtime.h>
#include <cuda_bf16.h>
#include <cstdint>

// ---------------- problem constants ----------------
#define TOK   25088      // B*N
#define CDIM  768
#define NQKV  2304
#define HEADS 12
#define EDIM  64
#define NBH   96
#define SDIM  3136
#define EPSV  1e-4f
#define KSPLIT 7
#define SCHUNK (SDIM / KSPLIT)   // 448

// ---------------- scratch (__device__ globals; no allocs allowed) ----------
__device__ float g_q   [(size_t)TOK * CDIM];
__device__ float g_k   [(size_t)TOK * CDIM];
__device__ float g_v   [(size_t)TOK * CDIM];
__device__ float g_attn[(size_t)TOK * CDIM];
__device__ float g_kv  [NBH * EDIM * EDIM];
__device__ float g_ksum[NBH * EDIM];
__device__ float g_kvp [KSPLIT * NBH * EDIM * EDIM];
__device__ float g_ksp [KSPLIT * NBH * EDIM];

__device__ __nv_bfloat16 g_xh [(size_t)TOK * CDIM];
__device__ __nv_bfloat16 g_xl [(size_t)TOK * CDIM];
__device__ __nv_bfloat16 g_ah [(size_t)TOK * CDIM];
__device__ __nv_bfloat16 g_al [(size_t)TOK * CDIM];
__device__ __nv_bfloat16 g_wqh[(size_t)NQKV * CDIM];
__device__ __nv_bfloat16 g_wql[(size_t)NQKV * CDIM];
__device__ __nv_bfloat16 g_wph[(size_t)CDIM * CDIM];
__device__ __nv_bfloat16 g_wpl[(size_t)CDIM * CDIM];

// ---------------- PTX helpers (sm_80-level only; nothing 'a'-gated) --------
__device__ __forceinline__ uint32_t smem_to_u32(const void* p) {
    uint32_t a;
    asm("{ .reg .u64 t; cvta.to.shared.u64 t, %1; cvt.u32.u64 %0, t; }"
        : "=r"(a) : "l"(p));
    return a;
}
__device__ __forceinline__ void cp16(uint32_t saddr, const void* gaddr) {
    asm volatile("cp.async.cg.shared.global [%0], [%1], 16;"
                 :: "r"(saddr), "l"(gaddr) : "memory");
}
#define CP_COMMIT() asm volatile("cp.async.commit_group;" ::: "memory")
#define CP_WAIT0()  asm volatile("cp.async.wait_group 0;" ::: "memory")

__device__ __forceinline__ void ldmx4(uint32_t* r, uint32_t addr) {
    asm volatile("ldmatrix.sync.aligned.m8n8.x4.shared.b16 {%0,%1,%2,%3}, [%4];"
                 : "=r"(r[0]), "=r"(r[1]), "=r"(r[2]), "=r"(r[3]) : "r"(addr));
}
__device__ __forceinline__ void mma_bf16(float* c, const uint32_t* a, const uint32_t* b) {
    asm volatile(
        "mma.sync.aligned.m16n8k16.row.col.f32.bf16.bf16.f32 "
        "{%0,%1,%2,%3}, {%4,%5,%6,%7}, {%8,%9}, {%0,%1,%2,%3};"
        : "+f"(c[0]), "+f"(c[1]), "+f"(c[2]), "+f"(c[3])
        : "r"(a[0]), "r"(a[1]), "r"(a[2]), "r"(a[3]), "r"(b[0]), "r"(b[1]));
}

// ---------------- GEMM tiling ----------------
#define LDS_T   40                     // bf16 per smem row (32 + 8 pad)
#define TILE_B  (128 * LDS_T * 2)      // 10240 bytes per operand tile
#define OFF_AH  0
#define OFF_AL  (1 * TILE_B)
#define OFF_BH  (2 * TILE_B)
#define OFF_BL  (3 * TILE_B)
#define STAGE_B (4 * TILE_B)           // 40960
#define GEMM_SMEM (2 * STAGE_B)        // 81920 (double buffered)
#define KTILES  (CDIM / 32)            // 24

// ---------------------------------------------------------------------------
// split fp32 -> (bf16 hi, bf16 lo)
// ---------------------------------------------------------------------------
__global__ void split_bf16(const float* __restrict__ src,
                           __nv_bfloat16* __restrict__ hi,
                           __nv_bfloat16* __restrict__ lo, int n4)
{
    int i = blockIdx.x * blockDim.x + threadIdx.x;
    if (i >= n4) return;
    float4 v = ((const float4*)src)[i];
    __nv_bfloat16 h0 = __float2bfloat16(v.x);
    __nv_bfloat16 h1 = __float2bfloat16(v.y);
    __nv_bfloat16 h2 = __float2bfloat16(v.z);
    __nv_bfloat16 h3 = __float2bfloat16(v.w);
    __nv_bfloat162* H = (__nv_bfloat162*)hi;
    __nv_bfloat162* L = (__nv_bfloat162*)lo;
    H[2 * i + 0] = __halves2bfloat162(h0, h1);
    H[2 * i + 1] = __halves2bfloat162(h2, h3);
    L[2 * i + 0] = __halves2bfloat162(__float2bfloat16(v.x - __bfloat162float(h0)),
                                      __float2bfloat16(v.y - __bfloat162float(h1)));
    L[2 * i + 1] = __halves2bfloat162(__float2bfloat16(v.z - __bfloat162float(h2)),
                                      __float2bfloat16(v.w - __bfloat162float(h3)));
}

// ---------------------------------------------------------------------------
// mma.sync TN GEMM, bf16 3-pass split: C[m,n] = sum_k A[m,k]*B[n,k], K=768.
// 128x128 tile, BK=32, 256 threads (8 warps, 2x4), warp tile 64x32,
// cp.async double-buffered. mode 0: qkv epilogue; mode 1: proj epilogue.
// ---------------------------------------------------------------------------
__global__ __launch_bounds__(256, 1) void gemm_mma(
    const __nv_bfloat16* __restrict__ Ah, const __nv_bfloat16* __restrict__ Al,
    const __nv_bfloat16* __restrict__ Bh, const __nv_bfloat16* __restrict__ Bl,
    const float* __restrict__ bias, float* __restrict__ Cout, int mode)
{
    extern __shared__ char smem[];
    const uint32_t sb  = smem_to_u32(smem);
    const int tid  = threadIdx.x;
    const int lane = tid & 31, wid = tid >> 5;
    const int bx = blockIdx.x, by = blockIdx.y;

    const int warp_m = wid & 1, warp_n = wid >> 1;   // 2 x 4 warp grid
    const int m0 = warp_m * 64, n0 = warp_n * 32;

    // ldmatrix per-lane address components
    const int a_row  = lane & 15;                 // A: row within 16
    const int a_kadd = (lane >> 4) * 8;           // A: k-half
    const int b_row  = (lane & 7) + ((lane >> 4) << 3);  // B: n within 16
    const int b_kadd = ((lane >> 3) & 1) * 8;     // B: k-half

    // per-thread cp.async source rows: idx = tid + i*256; row=idx&127; c=idx>>7
    float acc[4][4][4];
    #pragma unroll
    for (int i = 0; i < 4; i++)
        #pragma unroll
        for (int j = 0; j < 4; j++)
            #pragma unroll
            for (int c = 0; c < 4; c++) acc[i][j][c] = 0.0f;

    auto load_stage = [&](int stage, int kt) {
        const uint32_t s0 = sb + stage * STAGE_B;
        const int k0 = kt * 32;
        #pragma unroll
        for (int i = 0; i < 2; i++) {
            const int idx = tid + i * 256;
            const int row = idx & 127, cc = idx >> 7;     // cc in 0..3
            const uint32_t so = (uint32_t)(row * LDS_T + cc * 8) * 2;
            const size_t goA = (size_t)(by * 128 + row) * CDIM + k0 + cc * 8;
            const size_t goB = (size_t)(bx * 128 + row) * CDIM + k0 + cc * 8;
            cp16(s0 + OFF_AH + so, Ah + goA);
            cp16(s0 + OFF_AL + so, Al + goA);
            cp16(s0 + OFF_BH + so, Bh + goB);
            cp16(s0 + OFF_BL + so, Bl + goB);
        }
        CP_COMMIT();
    };

    auto compute_stage = [&](int stage) {
        const uint32_t s0 = sb + stage * STAGE_B;
        #pragma unroll
        for (int ks = 0; ks < 2; ks++) {
            const int kb = ks * 16;
            uint32_t ah[4][4], bh[2][4];
            #pragma unroll
            for (int am = 0; am < 4; am++)
                ldmx4(ah[am], s0 + OFF_AH +
                      (uint32_t)((m0 + am * 16 + a_row) * LDS_T + kb + a_kadd) * 2);
            #pragma unroll
            for (int p = 0; p < 2; p++)
                ldmx4(bh[p], s0 + OFF_BH +
                      (uint32_t)((n0 + p * 16 + b_row) * LDS_T + kb + b_kadd) * 2);
            #pragma unroll
            for (int am = 0; am < 4; am++)
                #pragma unroll
                for (int bn = 0; bn < 4; bn++)
                    mma_bf16(acc[am][bn], ah[am], &bh[bn >> 1][(bn & 1) * 2]);

            uint32_t bl[2][4];
            #pragma unroll
            for (int p = 0; p < 2; p++)
                ldmx4(bl[p], s0 + OFF_BL +
                      (uint32_t)((n0 + p * 16 + b_row) * LDS_T + kb + b_kadd) * 2);
            #pragma unroll
            for (int am = 0; am < 4; am++)
                #pragma unroll
                for (int bn = 0; bn < 4; bn++)
                    mma_bf16(acc[am][bn], ah[am], &bl[bn >> 1][(bn & 1) * 2]);

            uint32_t al[4][4];
            #pragma unroll
            for (int am = 0; am < 4; am++)
                ldmx4(al[am], s0 + OFF_AL +
                      (uint32_t)((m0 + am * 16 + a_row) * LDS_T + kb + a_kadd) * 2);
            #pragma unroll
            for (int am = 0; am < 4; am++)
                #pragma unroll
                for (int bn = 0; bn < 4; bn++)
                    mma_bf16(acc[am][bn], al[am], &bh[bn >> 1][(bn & 1) * 2]);
        }
    };

    load_stage(0, 0);
    for (int kt = 0; kt < KTILES; kt++) {
        CP_WAIT0();
        __syncthreads();                 // stage kt ready; prev buffer consumed
        if (kt + 1 < KTILES) load_stage((kt + 1) & 1, kt + 1);
        compute_stage(kt & 1);
    }

    // ---------------- epilogue: direct register -> gmem (float2 stores) -----
    const int rbase = by * 128 + m0;
    const int crow  = lane >> 2;          // 0..7
    const int ccol  = (lane & 3) * 2;

    if (mode == 0) {
        const int which = (bx * 128) / CDIM;          // 0:q 1:k 2:v
        float* dst = (which == 0) ? g_q : (which == 1) ? g_k : g_v;
        const bool rl = (which < 2);
        const int cbase = bx * 128 - which * CDIM + n0;
        #pragma unroll
        for (int am = 0; am < 4; am++) {
            #pragma unroll
            for (int bn = 0; bn < 4; bn++) {
                const int row = rbase + am * 16 + crow;
                const int col = cbase + bn * 8 + ccol;
                float2 v0 = make_float2(acc[am][bn][0], acc[am][bn][1]);
                float2 v1 = make_float2(acc[am][bn][2], acc[am][bn][3]);
                if (rl) {
                    v0.x = fmaxf(v0.x, 0.f); v0.y = fmaxf(v0.y, 0.f);
                    v1.x = fmaxf(v1.x, 0.f); v1.y = fmaxf(v1.y, 0.f);
                }
                *(float2*)(dst + (size_t)row * CDIM + col)       = v0;
                *(float2*)(dst + (size_t)(row + 8) * CDIM + col) = v1;
            }
        }
    } else {
        const int cbase = bx * 128 + n0;
        #pragma unroll
        for (int am = 0; am < 4; am++) {
            #pragma unroll
            for (int bn = 0; bn < 4; bn++) {
                const int row = rbase + am * 16 + crow;
                const int col = cbase + bn * 8 + ccol;
                const float b0 = bias[col], b1 = bias[col + 1];
                float2 v0 = make_float2(acc[am][bn][0] + b0, acc[am][bn][1] + b1);
                float2 v1 = make_float2(acc[am][bn][2] + b0, acc[am][bn][3] + b1);
                *(float2*)(Cout + (size_t)row * CDIM + col)       = v0;
                *(float2*)(Cout + (size_t)(row + 8) * CDIM + col) = v1;
            }
        }
    }
}

// ---------------------------------------------------------------------------
// kv partial: per (bh, s-split) accumulate kv outer products + ksum
// ---------------------------------------------------------------------------
__global__ __launch_bounds__(256) void kv_partial()
{
    const int bh = blockIdx.x;          // 0..95
    const int sp = blockIdx.y;          // 0..6
    const int b  = bh / HEADS;
    const int h  = bh % HEADS;
    const float* kbase = g_k + (size_t)b * SDIM * CDIM + h * EDIM;
    const float* vbase = g_v + (size_t)b * SDIM * CDIM + h * EDIM;

    __shared__ float ks[8][EDIM];
    __shared__ float vs[8][EDIM];

    const int tid = threadIdx.x;
    const int tx  = tid & 15, ty = tid >> 4;

    float acc[4][4];
    #pragma unroll
    for (int i = 0; i < 4; i++)
        #pragma unroll
        for (int j = 0; j < 4; j++) acc[i][j] = 0.0f;
    float ksum = 0.0f;

    const int s_beg = sp * SCHUNK, s_end = s_beg + SCHUNK;
    for (int s0 = s_beg; s0 < s_end; s0 += 8) {
        for (int i = tid; i < 8 * EDIM; i += 256) {
            const int sr = i >> 6, e = i & 63;
            ks[sr][e] = kbase[(size_t)(s0 + sr) * CDIM + e];
            vs[sr][e] = vbase[(size_t)(s0 + sr) * CDIM + e];
        }
        __syncthreads();
        #pragma unroll
        for (int sr = 0; sr < 8; sr++) {
            float rk[4], rv[4];
            #pragma unroll
            for (int i = 0; i < 4; i++) rk[i] = ks[sr][ty * 4 + i];
            #pragma unroll
            for (int j = 0; j < 4; j++) rv[j] = vs[sr][tx * 4 + j];
            #pragma unroll
            for (int i = 0; i < 4; i++)
                #pragma unroll
                for (int j = 0; j < 4; j++)
                    acc[i][j] = fmaf(rk[i], rv[j], acc[i][j]);
            if (tid < EDIM) ksum += ks[sr][tid];
        }
        __syncthreads();
    }

    float* kvout = g_kvp + ((size_t)sp * NBH + bh) * EDIM * EDIM;
    #pragma unroll
    for (int i = 0; i < 4; i++)
        #pragma unroll
        for (int j = 0; j < 4; j++)
            kvout[(ty * 4 + i) * EDIM + tx * 4 + j] = acc[i][j];
    if (tid < EDIM) g_ksp[((size_t)sp * NBH + bh) * EDIM + tid] = ksum;
}

__global__ __launch_bounds__(256) void kv_final()
{
    const int bh = blockIdx.x;
    const int tid = threadIdx.x;
    for (int i = tid; i < EDIM * EDIM; i += 256) {
        float s = 0.0f;
        #pragma unroll
        for (int sp = 0; sp < KSPLIT; sp++)
            s += g_kvp[((size_t)sp * NBH + bh) * EDIM * EDIM + i];
        g_kv[(size_t)bh * EDIM * EDIM + i] = s;
    }
    if (tid < EDIM) {
        float s = 0.0f;
        #pragma unroll
        for (int sp = 0; sp < KSPLIT; sp++)
            s += g_ksp[((size_t)sp * NBH + bh) * EDIM + tid];
        g_ksum[bh * EDIM + tid] = s;
    }
}

// ---------------------------------------------------------------------------
// attention output: out = (q @ kv) * z -> g_attn
// ---------------------------------------------------------------------------
__global__ __launch_bounds__(256) void attn_out()
{
    const int bh = blockIdx.x;
    const int st = blockIdx.y;
    const int b  = bh / HEADS;
    const int h  = bh % HEADS;

    __shared__ float kvs[EDIM][EDIM + 1];
    __shared__ float qs [EDIM][EDIM + 1];
    __shared__ float ksum_s[EDIM];
    __shared__ float zs[EDIM];

    const int tid = threadIdx.x;
    const int tx  = tid & 15, ty = tid >> 4;

    const float* qbase  = g_q + (size_t)(b * SDIM + st * 64) * CDIM + h * EDIM;
    const float* kvbase = g_kv + (size_t)bh * EDIM * EDIM;

    for (int i = tid; i < EDIM * EDIM; i += 256) {
        const int r = i >> 6, c = i & 63;
        kvs[r][c] = kvbase[i];
        qs [r][c] = qbase[(size_t)r * CDIM + c];
    }
    if (tid < EDIM) ksum_s[tid] = g_ksum[bh * EDIM + tid];
    __syncthreads();

    if (tid < EDIM) {
        float d = 0.0f;
        #pragma unroll
        for (int e = 0; e < EDIM; e++) d = fmaf(qs[tid][e], ksum_s[e], d);
        zs[tid] = 1.0f / (d + EPSV);
    }
    __syncthreads();

    float acc[4][4];
    #pragma unroll
    for (int i = 0; i < 4; i++)
        #pragma unroll
        for (int j = 0; j < 4; j++) acc[i][j] = 0.0f;

    #pragma unroll 8
    for (int e = 0; e < EDIM; e++) {
        float rq[4], rkv[4];
        #pragma unroll
        for (int i = 0; i < 4; i++) rq[i] = qs[ty * 4 + i][e];
        #pragma unroll
        for (int j = 0; j < 4; j++) rkv[j] = kvs[e][tx * 4 + j];
        #pragma unroll
        for (int i = 0; i < 4; i++)
            #pragma unroll
            for (int j = 0; j < 4; j++)
                acc[i][j] = fmaf(rq[i], rkv[j], acc[i][j]);
    }

    #pragma unroll
    for (int i = 0; i < 4; i++) {
        const int s = ty * 4 + i;
        const size_t token = (size_t)(b * SDIM + st * 64 + s);
        float* drow = g_attn + token * CDIM + h * EDIM + tx * 4;
        const float z = zs[s];
        #pragma unroll
        for (int j = 0; j < 4; j++)
            drow[j] = acc[i][j] * z;
    }
}

// ---------------------------------------------------------------------------
extern "C" void kernel_launch(void* const* d_in, const int* in_sizes, int n_in,
                              void* d_out, int out_size)
{
    const float* x     = (const float*)d_in[0];
    const float* Wqkv  = (const float*)d_in[1];
    const float* Wproj = (const float*)d_in[2];
    const float* bproj = (const float*)d_in[3];
    float* out = (float*)d_out;

    static int init_done = 0;
    if (!init_done) {
        cudaFuncSetAttribute(gemm_mma,
                             cudaFuncAttributeMaxDynamicSharedMemorySize, GEMM_SMEM);
        init_done = 1;
    }

    __nv_bfloat16 *xh, *xl, *ah, *al, *wqh, *wql, *wph, *wpl;
    cudaGetSymbolAddress((void**)&xh,  g_xh);
    cudaGetSymbolAddress((void**)&xl,  g_xl);
    cudaGetSymbolAddress((void**)&ah,  g_ah);
    cudaGetSymbolAddress((void**)&al,  g_al);
    cudaGetSymbolAddress((void**)&wqh, g_wqh);
    cudaGetSymbolAddress((void**)&wql, g_wql);
    cudaGetSymbolAddress((void**)&wph, g_wph);
    cudaGetSymbolAddress((void**)&wpl, g_wpl);
    float* attn;
    cudaGetSymbolAddress((void**)&attn, g_attn);

    // 1) fp32 -> bf16 hi/lo splits
    {
        int n4 = (TOK * CDIM) / 4;
        split_bf16<<<(n4 + 255) / 256, 256>>>(x, xh, xl, n4);
        n4 = (NQKV * CDIM) / 4;
        split_bf16<<<(n4 + 255) / 256, 256>>>(Wqkv, wqh, wql, n4);
        n4 = (CDIM * CDIM) / 4;
        split_bf16<<<(n4 + 255) / 256, 256>>>(Wproj, wph, wpl, n4);
    }
    // 2) qkv GEMM (tensor core mma.sync) -> g_q/g_k/g_v (relu on q,k)
    gemm_mma<<<dim3(NQKV / 128, TOK / 128), 256, GEMM_SMEM>>>(
        xh, xl, wqh, wql, nullptr, nullptr, 0);
    // 3) kv reduction (split over S) + combine
    kv_partial<<<dim3(NBH, KSPLIT), 256>>>();
    kv_final<<<NBH, 256>>>();
    // 4) attention output -> g_attn
    attn_out<<<dim3(NBH, SDIM / 64), 256>>>();
    // 5) split attn, proj GEMM -> out
    {
        int n4 = (TOK * CDIM) / 4;
        split_bf16<<<(n4 + 255) / 256, 256>>>(attn, ah, al, n4);
    }
    gemm_mma<<<dim3(CDIM / 128, TOK / 128), 256, GEMM_SMEM>>>(
        ah, al, wph, wpl, bproj, out, 1);
}

// round 8
// speedup vs baseline: 2.3860x; 1.1413x over previous
#include <cuda_runtime.h>
#include <cuda_bf16.h>
#include <cstdint>

// ---------------- problem constants ----------------
#define TOK   25088      // B*N
#define CDIM  768
#define NQKV  2304
#define HEADS 12
#define EDIM  64
#define NBH   96
#define SDIM  3136
#define EPSV  1e-4f
#define KSPLIT 7
#define SCHUNK (SDIM / KSPLIT)   // 448

// ---------------- scratch (__device__ globals; no allocs allowed) ----------
__device__ float g_q   [(size_t)TOK * CDIM];
__device__ float g_k   [(size_t)TOK * CDIM];
__device__ float g_v   [(size_t)TOK * CDIM];
__device__ float g_kv  [NBH * EDIM * EDIM];
__device__ float g_ksum[NBH * EDIM];
__device__ float g_kvp [KSPLIT * NBH * EDIM * EDIM];
__device__ float g_ksp [KSPLIT * NBH * EDIM];

__device__ __nv_bfloat16 g_xh [(size_t)TOK * CDIM];
__device__ __nv_bfloat16 g_xl [(size_t)TOK * CDIM];
__device__ __nv_bfloat16 g_ah [(size_t)TOK * CDIM];
__device__ __nv_bfloat16 g_al [(size_t)TOK * CDIM];
__device__ __nv_bfloat16 g_wqh[(size_t)NQKV * CDIM];
__device__ __nv_bfloat16 g_wql[(size_t)NQKV * CDIM];
__device__ __nv_bfloat16 g_wph[(size_t)CDIM * CDIM];
__device__ __nv_bfloat16 g_wpl[(size_t)CDIM * CDIM];

// ---------------- PTX helpers (sm_80-level only; nothing 'a'-gated) --------
__device__ __forceinline__ uint32_t smem_to_u32(const void* p) {
    uint32_t a;
    asm("{ .reg .u64 t; cvta.to.shared.u64 t, %1; cvt.u32.u64 %0, t; }"
        : "=r"(a) : "l"(p));
    return a;
}
__device__ __forceinline__ void cp16(uint32_t saddr, const void* gaddr) {
    asm volatile("cp.async.cg.shared.global [%0], [%1], 16;"
                 :: "r"(saddr), "l"(gaddr) : "memory");
}
#define CP_COMMIT() asm volatile("cp.async.commit_group;" ::: "memory")
#define CP_WAIT0()  asm volatile("cp.async.wait_group 0;" ::: "memory")

__device__ __forceinline__ void ldmx4(uint32_t* r, uint32_t addr) {
    asm volatile("ldmatrix.sync.aligned.m8n8.x4.shared.b16 {%0,%1,%2,%3}, [%4];"
                 : "=r"(r[0]), "=r"(r[1]), "=r"(r[2]), "=r"(r[3]) : "r"(addr));
}
__device__ __forceinline__ void mma_bf16(float* c, const uint32_t* a, const uint32_t* b) {
    asm volatile(
        "mma.sync.aligned.m16n8k16.row.col.f32.bf16.bf16.f32 "
        "{%0,%1,%2,%3}, {%4,%5,%6,%7}, {%8,%9}, {%0,%1,%2,%3};"
        : "+f"(c[0]), "+f"(c[1]), "+f"(c[2]), "+f"(c[3])
        : "r"(a[0]), "r"(a[1]), "r"(a[2]), "r"(a[3]), "r"(b[0]), "r"(b[1]));
}

// ---------------- GEMM tiling ----------------
#define LDS_T   40                     // bf16 per smem row (32 + 8 pad)
#define TILE_B  (128 * LDS_T * 2)      // 10240 bytes per operand tile
#define OFF_AH  0
#define OFF_AL  (1 * TILE_B)
#define OFF_BH  (2 * TILE_B)
#define OFF_BL  (3 * TILE_B)
#define STAGE_B (4 * TILE_B)           // 40960
#define GEMM_SMEM (2 * STAGE_B)        // 81920 (double buffered)
#define KTILES  (CDIM / 32)            // 24

// ---------------------------------------------------------------------------
// split fp32 -> (bf16 hi, bf16 lo)
// ---------------------------------------------------------------------------
__global__ void split_bf16(const float* __restrict__ src,
                           __nv_bfloat16* __restrict__ hi,
                           __nv_bfloat16* __restrict__ lo, int n4)
{
    int i = blockIdx.x * blockDim.x + threadIdx.x;
    if (i >= n4) return;
    float4 v = ((const float4*)src)[i];
    __nv_bfloat16 h0 = __float2bfloat16(v.x);
    __nv_bfloat16 h1 = __float2bfloat16(v.y);
    __nv_bfloat16 h2 = __float2bfloat16(v.z);
    __nv_bfloat16 h3 = __float2bfloat16(v.w);
    __nv_bfloat162* H = (__nv_bfloat162*)hi;
    __nv_bfloat162* L = (__nv_bfloat162*)lo;
    H[2 * i + 0] = __halves2bfloat162(h0, h1);
    H[2 * i + 1] = __halves2bfloat162(h2, h3);
    L[2 * i + 0] = __halves2bfloat162(__float2bfloat16(v.x - __bfloat162float(h0)),
                                      __float2bfloat16(v.y - __bfloat162float(h1)));
    L[2 * i + 1] = __halves2bfloat162(__float2bfloat16(v.z - __bfloat162float(h2)),
                                      __float2bfloat16(v.w - __bfloat162float(h3)));
}

// ---------------------------------------------------------------------------
// mma.sync TN GEMM, bf16 3-pass split: C[m,n] = sum_k A[m,k]*B[n,k], K=768.
// 128x128 tile, BK=32, 256 threads (8 warps, 2x4), warp tile 64x32,
// cp.async double-buffered. 2 CTAs/SM (regs capped at 128).
// mode 0: qkv epilogue; mode 1: proj epilogue.
// ---------------------------------------------------------------------------
__global__ __launch_bounds__(256, 2) void gemm_mma(
    const __nv_bfloat16* __restrict__ Ah, const __nv_bfloat16* __restrict__ Al,
    const __nv_bfloat16* __restrict__ Bh, const __nv_bfloat16* __restrict__ Bl,
    const float* __restrict__ bias, float* __restrict__ Cout, int mode)
{
    extern __shared__ char smem[];
    const uint32_t sb  = smem_to_u32(smem);
    const int tid  = threadIdx.x;
    const int lane = tid & 31, wid = tid >> 5;
    const int bx = blockIdx.x, by = blockIdx.y;

    const int warp_m = wid & 1, warp_n = wid >> 1;   // 2 x 4 warp grid
    const int m0 = warp_m * 64, n0 = warp_n * 32;

    // precomputed per-lane ldmatrix byte offsets (within a stage)
    const uint32_t a_off = (uint32_t)((m0 + (lane & 15)) * LDS_T + (lane >> 4) * 8) * 2;
    const uint32_t b_off = (uint32_t)((n0 + (lane & 7) + ((lane >> 4) << 3)) * LDS_T
                                      + ((lane >> 3) & 1) * 8) * 2;

    float acc[4][4][4];
    #pragma unroll
    for (int i = 0; i < 4; i++)
        #pragma unroll
        for (int j = 0; j < 4; j++)
            #pragma unroll
            for (int c = 0; c < 4; c++) acc[i][j][c] = 0.0f;

    // cp.async lane mapping
    const int ld_row0 = tid & 127, ld_cc0 = tid >> 7;
    const int ld_row1 = ld_row0, ld_cc1 = ld_cc0 + 2;

    auto load_stage = [&](int stage, int kt) {
        const uint32_t s0 = sb + stage * STAGE_B;
        const int k0 = kt * 32;
        {
            const uint32_t so = (uint32_t)(ld_row0 * LDS_T + ld_cc0 * 8) * 2;
            const size_t goA = (size_t)(by * 128 + ld_row0) * CDIM + k0 + ld_cc0 * 8;
            const size_t goB = (size_t)(bx * 128 + ld_row0) * CDIM + k0 + ld_cc0 * 8;
            cp16(s0 + OFF_AH + so, Ah + goA);
            cp16(s0 + OFF_AL + so, Al + goA);
            cp16(s0 + OFF_BH + so, Bh + goB);
            cp16(s0 + OFF_BL + so, Bl + goB);
        }
        {
            const uint32_t so = (uint32_t)(ld_row1 * LDS_T + ld_cc1 * 8) * 2;
            const size_t goA = (size_t)(by * 128 + ld_row1) * CDIM + k0 + ld_cc1 * 8;
            const size_t goB = (size_t)(bx * 128 + ld_row1) * CDIM + k0 + ld_cc1 * 8;
            cp16(s0 + OFF_AH + so, Ah + goA);
            cp16(s0 + OFF_AL + so, Al + goA);
            cp16(s0 + OFF_BH + so, Bh + goB);
            cp16(s0 + OFF_BL + so, Bl + goB);
        }
        CP_COMMIT();
    };

    auto compute_stage = [&](int stage) {
        const uint32_t s0 = sb + stage * STAGE_B;
        #pragma unroll
        for (int ks = 0; ks < 2; ks++) {
            const uint32_t kb = (uint32_t)(ks * 16) * 2;
            uint32_t ah[4][4], bh[2][4];
            #pragma unroll
            for (int am = 0; am < 4; am++)
                ldmx4(ah[am], s0 + OFF_AH + a_off + kb + (uint32_t)(am * 16 * LDS_T) * 2);
            #pragma unroll
            for (int p = 0; p < 2; p++)
                ldmx4(bh[p], s0 + OFF_BH + b_off + kb + (uint32_t)(p * 16 * LDS_T) * 2);
            #pragma unroll
            for (int am = 0; am < 4; am++)
                #pragma unroll
                for (int bn = 0; bn < 4; bn++)
                    mma_bf16(acc[am][bn], ah[am], &bh[bn >> 1][(bn & 1) * 2]);

            uint32_t bl[2][4];
            #pragma unroll
            for (int p = 0; p < 2; p++)
                ldmx4(bl[p], s0 + OFF_BL + b_off + kb + (uint32_t)(p * 16 * LDS_T) * 2);
            #pragma unroll
            for (int am = 0; am < 4; am++)
                #pragma unroll
                for (int bn = 0; bn < 4; bn++)
                    mma_bf16(acc[am][bn], ah[am], &bl[bn >> 1][(bn & 1) * 2]);

            uint32_t al[4][4];
            #pragma unroll
            for (int am = 0; am < 4; am++)
                ldmx4(al[am], s0 + OFF_AL + a_off + kb + (uint32_t)(am * 16 * LDS_T) * 2);
            #pragma unroll
            for (int am = 0; am < 4; am++)
                #pragma unroll
                for (int bn = 0; bn < 4; bn++)
                    mma_bf16(acc[am][bn], al[am], &bh[bn >> 1][(bn & 1) * 2]);
        }
    };

    load_stage(0, 0);
    for (int kt = 0; kt < KTILES; kt++) {
        CP_WAIT0();
        __syncthreads();
        if (kt + 1 < KTILES) load_stage((kt + 1) & 1, kt + 1);
        compute_stage(kt & 1);
    }

    // ---------------- epilogue: direct register -> gmem (float2 stores) -----
    const int rbase = by * 128 + m0;
    const int crow  = lane >> 2;          // 0..7
    const int ccol  = (lane & 3) * 2;

    if (mode == 0) {
        const int which = (bx * 128) / CDIM;          // 0:q 1:k 2:v
        float* dst = (which == 0) ? g_q : (which == 1) ? g_k : g_v;
        const bool rl = (which < 2);
        const int cbase = bx * 128 - which * CDIM + n0;
        #pragma unroll
        for (int am = 0; am < 4; am++) {
            #pragma unroll
            for (int bn = 0; bn < 4; bn++) {
                const int row = rbase + am * 16 + crow;
                const int col = cbase + bn * 8 + ccol;
                float2 v0 = make_float2(acc[am][bn][0], acc[am][bn][1]);
                float2 v1 = make_float2(acc[am][bn][2], acc[am][bn][3]);
                if (rl) {
                    v0.x = fmaxf(v0.x, 0.f); v0.y = fmaxf(v0.y, 0.f);
                    v1.x = fmaxf(v1.x, 0.f); v1.y = fmaxf(v1.y, 0.f);
                }
                *(float2*)(dst + (size_t)row * CDIM + col)       = v0;
                *(float2*)(dst + (size_t)(row + 8) * CDIM + col) = v1;
            }
        }
    } else {
        const int cbase = bx * 128 + n0;
        #pragma unroll
        for (int am = 0; am < 4; am++) {
            #pragma unroll
            for (int bn = 0; bn < 4; bn++) {
                const int row = rbase + am * 16 + crow;
                const int col = cbase + bn * 8 + ccol;
                const float b0 = bias[col], b1 = bias[col + 1];
                float2 v0 = make_float2(acc[am][bn][0] + b0, acc[am][bn][1] + b1);
                float2 v1 = make_float2(acc[am][bn][2] + b0, acc[am][bn][3] + b1);
                *(float2*)(Cout + (size_t)row * CDIM + col)       = v0;
                *(float2*)(Cout + (size_t)(row + 8) * CDIM + col) = v1;
            }
        }
    }
}

// ---------------------------------------------------------------------------
// kv partial: per (bh, s-split) accumulate kv outer products + ksum
// ---------------------------------------------------------------------------
__global__ __launch_bounds__(256) void kv_partial()
{
    const int bh = blockIdx.x;          // 0..95
    const int sp = blockIdx.y;          // 0..6
    const int b  = bh / HEADS;
    const int h  = bh % HEADS;
    const float* kbase = g_k + (size_t)b * SDIM * CDIM + h * EDIM;
    const float* vbase = g_v + (size_t)b * SDIM * CDIM + h * EDIM;

    __shared__ float ks[8][EDIM];
    __shared__ float vs[8][EDIM];

    const int tid = threadIdx.x;
    const int tx  = tid & 15, ty = tid >> 4;

    float acc[4][4];
    #pragma unroll
    for (int i = 0; i < 4; i++)
        #pragma unroll
        for (int j = 0; j < 4; j++) acc[i][j] = 0.0f;
    float ksum = 0.0f;

    const int s_beg = sp * SCHUNK, s_end = s_beg + SCHUNK;
    for (int s0 = s_beg; s0 < s_end; s0 += 8) {
        for (int i = tid; i < 8 * EDIM; i += 256) {
            const int sr = i >> 6, e = i & 63;
            ks[sr][e] = kbase[(size_t)(s0 + sr) * CDIM + e];
            vs[sr][e] = vbase[(size_t)(s0 + sr) * CDIM + e];
        }
        __syncthreads();
        #pragma unroll
        for (int sr = 0; sr < 8; sr++) {
            float rk[4], rv[4];
            #pragma unroll
            for (int i = 0; i < 4; i++) rk[i] = ks[sr][ty * 4 + i];
            #pragma unroll
            for (int j = 0; j < 4; j++) rv[j] = vs[sr][tx * 4 + j];
            #pragma unroll
            for (int i = 0; i < 4; i++)
                #pragma unroll
                for (int j = 0; j < 4; j++)
                    acc[i][j] = fmaf(rk[i], rv[j], acc[i][j]);
            if (tid < EDIM) ksum += ks[sr][tid];
        }
        __syncthreads();
    }

    float* kvout = g_kvp + ((size_t)sp * NBH + bh) * EDIM * EDIM;
    #pragma unroll
    for (int i = 0; i < 4; i++)
        #pragma unroll
        for (int j = 0; j < 4; j++)
            kvout[(ty * 4 + i) * EDIM + tx * 4 + j] = acc[i][j];
    if (tid < EDIM) g_ksp[((size_t)sp * NBH + bh) * EDIM + tid] = ksum;
}

__global__ __launch_bounds__(256) void kv_final()
{
    const int bh = blockIdx.x;
    const int tid = threadIdx.x;
    for (int i = tid; i < EDIM * EDIM; i += 256) {
        float s = 0.0f;
        #pragma unroll
        for (int sp = 0; sp < KSPLIT; sp++)
            s += g_kvp[((size_t)sp * NBH + bh) * EDIM * EDIM + i];
        g_kv[(size_t)bh * EDIM * EDIM + i] = s;
    }
    if (tid < EDIM) {
        float s = 0.0f;
        #pragma unroll
        for (int sp = 0; sp < KSPLIT; sp++)
            s += g_ksp[((size_t)sp * NBH + bh) * EDIM + tid];
        g_ksum[bh * EDIM + tid] = s;
    }
}

// ---------------------------------------------------------------------------
// attention output: out = (q @ kv) * z  -> written directly as bf16 hi/lo
// (fused split; removes the f32 g_attn round trip)
// ---------------------------------------------------------------------------
__global__ __launch_bounds__(256) void attn_out()
{
    const int bh = blockIdx.x;
    const int st = blockIdx.y;
    const int b  = bh / HEADS;
    const int h  = bh % HEADS;

    __shared__ float kvs[EDIM][EDIM + 1];
    __shared__ float qs [EDIM][EDIM + 1];
    __shared__ float ksum_s[EDIM];
    __shared__ float zs[EDIM];

    const int tid = threadIdx.x;
    const int tx  = tid & 15, ty = tid >> 4;

    const float* qbase  = g_q + (size_t)(b * SDIM + st * 64) * CDIM + h * EDIM;
    const float* kvbase = g_kv + (size_t)bh * EDIM * EDIM;

    for (int i = tid; i < EDIM * EDIM; i += 256) {
        const int r = i >> 6, c = i & 63;
        kvs[r][c] = kvbase[i];
        qs [r][c] = qbase[(size_t)r * CDIM + c];
    }
    if (tid < EDIM) ksum_s[tid] = g_ksum[bh * EDIM + tid];
    __syncthreads();

    if (tid < EDIM) {
        float d = 0.0f;
        #pragma unroll
        for (int e = 0; e < EDIM; e++) d = fmaf(qs[tid][e], ksum_s[e], d);
        zs[tid] = 1.0f / (d + EPSV);
    }
    __syncthreads();

    float acc[4][4];
    #pragma unroll
    for (int i = 0; i < 4; i++)
        #pragma unroll
        for (int j = 0; j < 4; j++) acc[i][j] = 0.0f;

    #pragma unroll 8
    for (int e = 0; e < EDIM; e++) {
        float rq[4], rkv[4];
        #pragma unroll
        for (int i = 0; i < 4; i++) rq[i] = qs[ty * 4 + i][e];
        #pragma unroll
        for (int j = 0; j < 4; j++) rkv[j] = kvs[e][tx * 4 + j];
        #pragma unroll
        for (int i = 0; i < 4; i++)
            #pragma unroll
            for (int j = 0; j < 4; j++)
                acc[i][j] = fmaf(rq[i], rkv[j], acc[i][j]);
    }

    #pragma unroll
    for (int i = 0; i < 4; i++) {
        const int s = ty * 4 + i;
        const size_t token = (size_t)(b * SDIM + st * 64 + s);
        const float z = zs[s];
        __nv_bfloat162* hrow = (__nv_bfloat162*)(g_ah + token * CDIM + h * EDIM + tx * 4);
        __nv_bfloat162* lrow = (__nv_bfloat162*)(g_al + token * CDIM + h * EDIM + tx * 4);
        #pragma unroll
        for (int j2 = 0; j2 < 2; j2++) {
            float f0 = acc[i][j2 * 2 + 0] * z;
            float f1 = acc[i][j2 * 2 + 1] * z;
            __nv_bfloat16 h0 = __float2bfloat16(f0);
            __nv_bfloat16 h1 = __float2bfloat16(f1);
            hrow[j2] = __halves2bfloat162(h0, h1);
            lrow[j2] = __halves2bfloat162(__float2bfloat16(f0 - __bfloat162float(h0)),
                                          __float2bfloat16(f1 - __bfloat162float(h1)));
        }
    }
}

// ---------------------------------------------------------------------------
extern "C" void kernel_launch(void* const* d_in, const int* in_sizes, int n_in,
                              void* d_out, int out_size)
{
    const float* x     = (const float*)d_in[0];
    const float* Wqkv  = (const float*)d_in[1];
    const float* Wproj = (const float*)d_in[2];
    const float* bproj = (const float*)d_in[3];
    float* out = (float*)d_out;

    static int init_done = 0;
    if (!init_done) {
        cudaFuncSetAttribute(gemm_mma,
                             cudaFuncAttributeMaxDynamicSharedMemorySize, GEMM_SMEM);
        init_done = 1;
    }

    __nv_bfloat16 *xh, *xl, *ah, *al, *wqh, *wql, *wph, *wpl;
    cudaGetSymbolAddress((void**)&xh,  g_xh);
    cudaGetSymbolAddress((void**)&xl,  g_xl);
    cudaGetSymbolAddress((void**)&ah,  g_ah);
    cudaGetSymbolAddress((void**)&al,  g_al);
    cudaGetSymbolAddress((void**)&wqh, g_wqh);
    cudaGetSymbolAddress((void**)&wql, g_wql);
    cudaGetSymbolAddress((void**)&wph, g_wph);
    cudaGetSymbolAddress((void**)&wpl, g_wpl);

    // 1) fp32 -> bf16 hi/lo splits (inputs)
    {
        int n4 = (TOK * CDIM) / 4;
        split_bf16<<<(n4 + 255) / 256, 256>>>(x, xh, xl, n4);
        n4 = (NQKV * CDIM) / 4;
        split_bf16<<<(n4 + 255) / 256, 256>>>(Wqkv, wqh, wql, n4);
        n4 = (CDIM * CDIM) / 4;
        split_bf16<<<(n4 + 255) / 256, 256>>>(Wproj, wph, wpl, n4);
    }
    // 2) qkv GEMM (tensor core mma.sync) -> g_q/g_k/g_v (relu on q,k)
    gemm_mma<<<dim3(NQKV / 128, TOK / 128), 256, GEMM_SMEM>>>(
        xh, xl, wqh, wql, nullptr, nullptr, 0);
    // 3) kv reduction (split over S) + combine
    kv_partial<<<dim3(NBH, KSPLIT), 256>>>();
    kv_final<<<NBH, 256>>>();
    // 4) attention output -> g_ah/g_al (fused bf16 split)
    attn_out<<<dim3(NBH, SDIM / 64), 256>>>();
    // 5) proj GEMM -> out
    gemm_mma<<<dim3(CDIM / 128, TOK / 128), 256, GEMM_SMEM>>>(
        ah, al, wph, wpl, bproj, out, 1);
}

// round 12
// speedup vs baseline: 3.0553x; 1.2805x over previous
#include <cuda_runtime.h>
#include <cuda_fp16.h>
#include <cstdint>

// ---------------- problem constants ----------------
#define TOK   25088      // B*N
#define CDIM  768
#define NQKV  2304
#define HEADS 12
#define EDIM  64
#define NBH   96
#define SDIM  3136
#define EPSV  1e-4f
#define KSPLIT 7
#define SCHUNK (SDIM / KSPLIT)   // 448

// ---------------- scratch (__device__ globals; no allocs allowed) ----------
__device__ float g_q   [(size_t)TOK * CDIM];
__device__ float g_k   [(size_t)TOK * CDIM];
__device__ float g_v   [(size_t)TOK * CDIM];
__device__ float g_kv  [NBH * EDIM * EDIM];
__device__ float g_ksum[NBH * EDIM];
__device__ float g_kvp [KSPLIT * NBH * EDIM * EDIM];
__device__ float g_ksp [KSPLIT * NBH * EDIM];

__device__ __half g_xh [(size_t)TOK * CDIM];
__device__ __half g_xl [(size_t)TOK * CDIM];
__device__ __half g_ah [(size_t)TOK * CDIM];
__device__ __half g_al [(size_t)TOK * CDIM];
__device__ __half g_wqh[(size_t)NQKV * CDIM];
__device__ __half g_wph[(size_t)CDIM * CDIM];

// ---------------- PTX helpers (sm_80-level only; nothing 'a'-gated) --------
__device__ __forceinline__ uint32_t smem_to_u32(const void* p) {
    uint32_t a;
    asm("{ .reg .u64 t; cvta.to.shared.u64 t, %1; cvt.u32.u64 %0, t; }"
        : "=r"(a) : "l"(p));
    return a;
}
__device__ __forceinline__ void cp16(uint32_t saddr, const void* gaddr) {
    asm volatile("cp.async.cg.shared.global [%0], [%1], 16;"
                 :: "r"(saddr), "l"(gaddr) : "memory");
}
#define CP_COMMIT() asm volatile("cp.async.commit_group;" ::: "memory")
#define CP_WAIT1()  asm volatile("cp.async.wait_group 1;" ::: "memory")

__device__ __forceinline__ void ldmx4(uint32_t* r, uint32_t addr) {
    asm volatile("ldmatrix.sync.aligned.m8n8.x4.shared.b16 {%0,%1,%2,%3}, [%4];"
                 : "=r"(r[0]), "=r"(r[1]), "=r"(r[2]), "=r"(r[3]) : "r"(addr));
}
__device__ __forceinline__ void mma_f16(float* c, const uint32_t* a, const uint32_t* b) {
    asm volatile(
        "mma.sync.aligned.m16n8k16.row.col.f32.f16.f16.f32 "
        "{%0,%1,%2,%3}, {%4,%5,%6,%7}, {%8,%9}, {%0,%1,%2,%3};"
        : "+f"(c[0]), "+f"(c[1]), "+f"(c[2]), "+f"(c[3])
        : "r"(a[0]), "r"(a[1]), "r"(a[2]), "r"(a[3]), "r"(b[0]), "r"(b[1]));
}

// ---------------- GEMM tiling ----------------
#define LDS_T   40                     // fp16 per smem row (32 + 8 pad)
#define TILE_B  (128 * LDS_T * 2)      // 10240 bytes per operand tile
#define OFF_AH  0
#define OFF_AL  (1 * TILE_B)
#define OFF_BH  (2 * TILE_B)
#define STAGE_B (3 * TILE_B)           // 30720
#define STAGES  3
#define GEMM_SMEM (STAGES * STAGE_B)   // 92160 (2 CTAs/SM -> 184320)
#define KTILES  (CDIM / 32)            // 24

// ---------------------------------------------------------------------------
// split fp32 -> (fp16 hi, fp16 lo)
// ---------------------------------------------------------------------------
__global__ void split_f16(const float* __restrict__ src,
                          __half* __restrict__ hi,
                          __half* __restrict__ lo, int n4)
{
    int i = blockIdx.x * blockDim.x + threadIdx.x;
    if (i >= n4) return;
    float4 v = ((const float4*)src)[i];
    __half h0 = __float2half_rn(v.x);
    __half h1 = __float2half_rn(v.y);
    __half h2 = __float2half_rn(v.z);
    __half h3 = __float2half_rn(v.w);
    __half2* H = (__half2*)hi;
    __half2* L = (__half2*)lo;
    H[2 * i + 0] = __halves2half2(h0, h1);
    H[2 * i + 1] = __halves2half2(h2, h3);
    L[2 * i + 0] = __halves2half2(__float2half_rn(v.x - __half2float(h0)),
                                  __float2half_rn(v.y - __half2float(h1)));
    L[2 * i + 1] = __halves2half2(__float2half_rn(v.z - __half2float(h2)),
                                  __float2half_rn(v.w - __half2float(h3)));
}

// round fp32 -> fp16 (weights: hi only)
__global__ void round_f16(const float* __restrict__ src,
                          __half* __restrict__ hi, int n4)
{
    int i = blockIdx.x * blockDim.x + threadIdx.x;
    if (i >= n4) return;
    float4 v = ((const float4*)src)[i];
    __half2* H = (__half2*)hi;
    H[2 * i + 0] = __halves2half2(__float2half_rn(v.x), __float2half_rn(v.y));
    H[2 * i + 1] = __halves2half2(__float2half_rn(v.z), __float2half_rn(v.w));
}

// ---------------------------------------------------------------------------
// mma.sync TN GEMM, fp16 2-pass split: C[m,n] = sum_k (Ah+Al)[m,k]*Bh[n,k].
// 128x128 tile, BK=32, 256 threads (8 warps, 2x4), warp tile 64x32,
// cp.async 3-stage pipeline, 2 CTAs/SM.
// mode 0: qkv epilogue; mode 1: proj epilogue.
// ---------------------------------------------------------------------------
__global__ __launch_bounds__(256, 2) void gemm_mma(
    const __half* __restrict__ Ah, const __half* __restrict__ Al,
    const __half* __restrict__ Bh,
    const float* __restrict__ bias, float* __restrict__ Cout, int mode)
{
    extern __shared__ char smem[];
    const uint32_t sb  = smem_to_u32(smem);
    const int tid  = threadIdx.x;
    const int lane = tid & 31, wid = tid >> 5;
    const int bx = blockIdx.x, by = blockIdx.y;

    const int warp_m = wid & 1, warp_n = wid >> 1;   // 2 x 4 warp grid
    const int m0 = warp_m * 64, n0 = warp_n * 32;

    // precomputed per-lane ldmatrix byte offsets (within a stage)
    const uint32_t a_off = (uint32_t)((m0 + (lane & 15)) * LDS_T + (lane >> 4) * 8) * 2;
    const uint32_t b_off = (uint32_t)((n0 + (lane & 7) + ((lane >> 4) << 3)) * LDS_T
                                      + ((lane >> 3) & 1) * 8) * 2;

    float acc[4][4][4];
    #pragma unroll
    for (int i = 0; i < 4; i++)
        #pragma unroll
        for (int j = 0; j < 4; j++)
            #pragma unroll
            for (int c = 0; c < 4; c++) acc[i][j][c] = 0.0f;

    // cp.async lane mapping: 256 threads cover 128 rows x 2 chunks; 2 iters
    const int ld_row = tid & 127, ld_cc0 = tid >> 7;   // cc0 in {0,1}

    auto load_stage = [&](int stage, int kt) {
        const uint32_t s0 = sb + stage * STAGE_B;
        const int k0 = kt * 32;
        #pragma unroll
        for (int i = 0; i < 2; i++) {
            const int cc = ld_cc0 + i * 2;           // 0..3
            const uint32_t so = (uint32_t)(ld_row * LDS_T + cc * 8) * 2;
            const size_t goA = (size_t)(by * 128 + ld_row) * CDIM + k0 + cc * 8;
            const size_t goB = (size_t)(bx * 128 + ld_row) * CDIM + k0 + cc * 8;
            cp16(s0 + OFF_AH + so, Ah + goA);
            cp16(s0 + OFF_AL + so, Al + goA);
            cp16(s0 + OFF_BH + so, Bh + goB);
        }
        CP_COMMIT();
    };

    auto compute_stage = [&](int stage) {
        const uint32_t s0 = sb + stage * STAGE_B;
        #pragma unroll
        for (int ks = 0; ks < 2; ks++) {
            const uint32_t kb = (uint32_t)(ks * 16) * 2;
            uint32_t ah[4][4], bh[2][4];
            #pragma unroll
            for (int am = 0; am < 4; am++)
                ldmx4(ah[am], s0 + OFF_AH + a_off + kb + (uint32_t)(am * 16 * LDS_T) * 2);
            #pragma unroll
            for (int p = 0; p < 2; p++)
                ldmx4(bh[p], s0 + OFF_BH + b_off + kb + (uint32_t)(p * 16 * LDS_T) * 2);
            #pragma unroll
            for (int am = 0; am < 4; am++)
                #pragma unroll
                for (int bn = 0; bn < 4; bn++)
                    mma_f16(acc[am][bn], ah[am], &bh[bn >> 1][(bn & 1) * 2]);

            uint32_t al[4][4];
            #pragma unroll
            for (int am = 0; am < 4; am++)
                ldmx4(al[am], s0 + OFF_AL + a_off + kb + (uint32_t)(am * 16 * LDS_T) * 2);
            #pragma unroll
            for (int am = 0; am < 4; am++)
                #pragma unroll
                for (int bn = 0; bn < 4; bn++)
                    mma_f16(acc[am][bn], al[am], &bh[bn >> 1][(bn & 1) * 2]);
        }
    };

    load_stage(0, 0);
    load_stage(1, 1);
    int buf = 0;
    for (int kt = 0; kt < KTILES; kt++) {
        CP_WAIT1();                      // group kt complete (<=1 pending)
        __syncthreads();                 // all warps done with buf being reloaded
        if (kt + 2 < KTILES) load_stage((kt + 2) % STAGES, kt + 2);
        compute_stage(buf);
        buf = (buf + 1) % STAGES;
    }

    // ---------------- epilogue: direct register -> gmem (float2 stores) -----
    const int rbase = by * 128 + m0;
    const int crow  = lane >> 2;          // 0..7
    const int ccol  = (lane & 3) * 2;

    if (mode == 0) {
        const int which = (bx * 128) / CDIM;          // 0:q 1:k 2:v
        float* dst = (which == 0) ? g_q : (which == 1) ? g_k : g_v;
        const bool rl = (which < 2);
        const int cbase = bx * 128 - which * CDIM + n0;
        #pragma unroll
        for (int am = 0; am < 4; am++) {
            #pragma unroll
            for (int bn = 0; bn < 4; bn++) {
                const int row = rbase + am * 16 + crow;
                const int col = cbase + bn * 8 + ccol;
                float2 v0 = make_float2(acc[am][bn][0], acc[am][bn][1]);
                float2 v1 = make_float2(acc[am][bn][2], acc[am][bn][3]);
                if (rl) {
                    v0.x = fmaxf(v0.x, 0.f); v0.y = fmaxf(v0.y, 0.f);
                    v1.x = fmaxf(v1.x, 0.f); v1.y = fmaxf(v1.y, 0.f);
                }
                *(float2*)(dst + (size_t)row * CDIM + col)       = v0;
                *(float2*)(dst + (size_t)(row + 8) * CDIM + col) = v1;
            }
        }
    } else {
        const int cbase = bx * 128 + n0;
        #pragma unroll
        for (int am = 0; am < 4; am++) {
            #pragma unroll
            for (int bn = 0; bn < 4; bn++) {
                const int row = rbase + am * 16 + crow;
                const int col = cbase + bn * 8 + ccol;
                const float b0 = bias[col], b1 = bias[col + 1];
                float2 v0 = make_float2(acc[am][bn][0] + b0, acc[am][bn][1] + b1);
                float2 v1 = make_float2(acc[am][bn][2] + b0, acc[am][bn][3] + b1);
                *(float2*)(Cout + (size_t)row * CDIM + col)       = v0;
                *(float2*)(Cout + (size_t)(row + 8) * CDIM + col) = v1;
            }
        }
    }
}

// ---------------------------------------------------------------------------
// kv partial: per (bh, s-split) accumulate kv outer products + ksum
// ---------------------------------------------------------------------------
__global__ __launch_bounds__(256) void kv_partial()
{
    const int bh = blockIdx.x;          // 0..95
    const int sp = blockIdx.y;          // 0..6
    const int b  = bh / HEADS;
    const int h  = bh % HEADS;
    const float* kbase = g_k + (size_t)b * SDIM * CDIM + h * EDIM;
    const float* vbase = g_v + (size_t)b * SDIM * CDIM + h * EDIM;

    __shared__ float ks[8][EDIM];
    __shared__ float vs[8][EDIM];

    const int tid = threadIdx.x;
    const int tx  = tid & 15, ty = tid >> 4;

    float acc[4][4];
    #pragma unroll
    for (int i = 0; i < 4; i++)
        #pragma unroll
        for (int j = 0; j < 4; j++) acc[i][j] = 0.0f;
    float ksum = 0.0f;

    const int s_beg = sp * SCHUNK, s_end = s_beg + SCHUNK;
    for (int s0 = s_beg; s0 < s_end; s0 += 8) {
        for (int i = tid; i < 8 * EDIM; i += 256) {
            const int sr = i >> 6, e = i & 63;
            ks[sr][e] = kbase[(size_t)(s0 + sr) * CDIM + e];
            vs[sr][e] = vbase[(size_t)(s0 + sr) * CDIM + e];
        }
        __syncthreads();
        #pragma unroll
        for (int sr = 0; sr < 8; sr++) {
            float rk[4], rv[4];
            #pragma unroll
            for (int i = 0; i < 4; i++) rk[i] = ks[sr][ty * 4 + i];
            #pragma unroll
            for (int j = 0; j < 4; j++) rv[j] = vs[sr][tx * 4 + j];
            #pragma unroll
            for (int i = 0; i < 4; i++)
                #pragma unroll
                for (int j = 0; j < 4; j++)
                    acc[i][j] = fmaf(rk[i], rv[j], acc[i][j]);
            if (tid < EDIM) ksum += ks[sr][tid];
        }
        __syncthreads();
    }

    float* kvout = g_kvp + ((size_t)sp * NBH + bh) * EDIM * EDIM;
    #pragma unroll
    for (int i = 0; i < 4; i++)
        #pragma unroll
        for (int j = 0; j < 4; j++)
            kvout[(ty * 4 + i) * EDIM + tx * 4 + j] = acc[i][j];
    if (tid < EDIM) g_ksp[((size_t)sp * NBH + bh) * EDIM + tid] = ksum;
}

__global__ __launch_bounds__(256) void kv_final()
{
    const int bh = blockIdx.x;
    const int tid = threadIdx.x;
    for (int i = tid; i < EDIM * EDIM; i += 256) {
        float s = 0.0f;
        #pragma unroll
        for (int sp = 0; sp < KSPLIT; sp++)
            s += g_kvp[((size_t)sp * NBH + bh) * EDIM * EDIM + i];
        g_kv[(size_t)bh * EDIM * EDIM + i] = s;
    }
    if (tid < EDIM) {
        float s = 0.0f;
        #pragma unroll
        for (int sp = 0; sp < KSPLIT; sp++)
            s += g_ksp[((size_t)sp * NBH + bh) * EDIM + tid];
        g_ksum[bh * EDIM + tid] = s;
    }
}

// ---------------------------------------------------------------------------
// attention output: out = (q @ kv) * z  -> written directly as fp16 hi/lo
// ---------------------------------------------------------------------------
__global__ __launch_bounds__(256) void attn_out()
{
    const int bh = blockIdx.x;
    const int st = blockIdx.y;
    const int b  = bh / HEADS;
    const int h  = bh % HEADS;

    __shared__ float kvs[EDIM][EDIM + 1];
    __shared__ float qs [EDIM][EDIM + 1];
    __shared__ float ksum_s[EDIM];
    __shared__ float zs[EDIM];

    const int tid = threadIdx.x;
    const int tx  = tid & 15, ty = tid >> 4;

    const float* qbase  = g_q + (size_t)(b * SDIM + st * 64) * CDIM + h * EDIM;
    const float* kvbase = g_kv + (size_t)bh * EDIM * EDIM;

    for (int i = tid; i < EDIM * EDIM; i += 256) {
        const int r = i >> 6, c = i & 63;
        kvs[r][c] = kvbase[i];
        qs [r][c] = qbase[(size_t)r * CDIM + c];
    }
    if (tid < EDIM) ksum_s[tid] = g_ksum[bh * EDIM + tid];
    __syncthreads();

    if (tid < EDIM) {
        float d = 0.0f;
        #pragma unroll
        for (int e = 0; e < EDIM; e++) d = fmaf(qs[tid][e], ksum_s[e], d);
        zs[tid] = 1.0f / (d + EPSV);
    }
    __syncthreads();

    float acc[4][4];
    #pragma unroll
    for (int i = 0; i < 4; i++)
        #pragma unroll
        for (int j = 0; j < 4; j++) acc[i][j] = 0.0f;

    #pragma unroll 8
    for (int e = 0; e < EDIM; e++) {
        float rq[4], rkv[4];
        #pragma unroll
        for (int i = 0; i < 4; i++) rq[i] = qs[ty * 4 + i][e];
        #pragma unroll
        for (int j = 0; j < 4; j++) rkv[j] = kvs[e][tx * 4 + j];
        #pragma unroll
        for (int i = 0; i < 4; i++)
            #pragma unroll
            for (int j = 0; j < 4; j++)
                acc[i][j] = fmaf(rq[i], rkv[j], acc[i][j]);
    }

    #pragma unroll
    for (int i = 0; i < 4; i++) {
        const int s = ty * 4 + i;
        const size_t token = (size_t)(b * SDIM + st * 64 + s);
        const float z = zs[s];
        __half2* hrow = (__half2*)(g_ah + token * CDIM + h * EDIM + tx * 4);
        __half2* lrow = (__half2*)(g_al + token * CDIM + h * EDIM + tx * 4);
        #pragma unroll
        for (int j2 = 0; j2 < 2; j2++) {
            float f0 = acc[i][j2 * 2 + 0] * z;
            float f1 = acc[i][j2 * 2 + 1] * z;
            __half h0 = __float2half_rn(f0);
            __half h1 = __float2half_rn(f1);
            hrow[j2] = __halves2half2(h0, h1);
            lrow[j2] = __halves2half2(__float2half_rn(f0 - __half2float(h0)),
                                      __float2half_rn(f1 - __half2float(h1)));
        }
    }
}

// ---------------------------------------------------------------------------
extern "C" void kernel_launch(void* const* d_in, const int* in_sizes, int n_in,
                              void* d_out, int out_size)
{
    const float* x     = (const float*)d_in[0];
    const float* Wqkv  = (const float*)d_in[1];
    const float* Wproj = (const float*)d_in[2];
    const float* bproj = (const float*)d_in[3];
    float* out = (float*)d_out;

    static int init_done = 0;
    if (!init_done) {
        cudaFuncSetAttribute(gemm_mma,
                             cudaFuncAttributeMaxDynamicSharedMemorySize, GEMM_SMEM);
        init_done = 1;
    }

    __half *xh, *xl, *ah, *al, *wqh, *wph;
    cudaGetSymbolAddress((void**)&xh,  g_xh);
    cudaGetSymbolAddress((void**)&xl,  g_xl);
    cudaGetSymbolAddress((void**)&ah,  g_ah);
    cudaGetSymbolAddress((void**)&al,  g_al);
    cudaGetSymbolAddress((void**)&wqh, g_wqh);
    cudaGetSymbolAddress((void**)&wph, g_wph);

    // 1) fp32 -> fp16 splits (x: hi+lo; weights: hi only)
    {
        int n4 = (TOK * CDIM) / 4;
        split_f16<<<(n4 + 255) / 256, 256>>>(x, xh, xl, n4);
        n4 = (NQKV * CDIM) / 4;
        round_f16<<<(n4 + 255) / 256, 256>>>(Wqkv, wqh, n4);
        n4 = (CDIM * CDIM) / 4;
        round_f16<<<(n4 + 255) / 256, 256>>>(Wproj, wph, n4);
    }
    // 2) qkv GEMM (tensor core mma.sync, fp16 2-pass) -> g_q/g_k/g_v
    gemm_mma<<<dim3(NQKV / 128, TOK / 128), 256, GEMM_SMEM>>>(
        xh, xl, wqh, nullptr, nullptr, 0);
    // 3) kv reduction (split over S) + combine
    kv_partial<<<dim3(NBH, KSPLIT), 256>>>();
    kv_final<<<NBH, 256>>>();
    // 4) attention output -> g_ah/g_al (fused fp16 split)
    attn_out<<<dim3(NBH, SDIM / 64), 256>>>();
    // 5) proj GEMM -> out
    gemm_mma<<<dim3(CDIM / 128, TOK / 128), 256, GEMM_SMEM>>>(
        ah, al, wph, bproj, out, 1);
}

// round 14
// speedup vs baseline: 4.1178x; 1.3478x over previous
#include <cuda_runtime.h>
#include <cuda_fp16.h>
#include <cstdint>

// ---------------- problem constants ----------------
#define TOK   25088      // B*N
#define CDIM  768
#define NQKV  2304
#define HEADS 12
#define EDIM  64
#define NBH   96
#define SDIM  3136
#define EPSV  1e-4f
#define KSPLIT 7
#define SCHUNK (SDIM / KSPLIT)   // 448

// ---------------- scratch (__device__ globals; no allocs allowed) ----------
__device__ float g_q   [(size_t)TOK * CDIM];
__device__ float g_k   [(size_t)TOK * CDIM];
__device__ float g_v   [(size_t)TOK * CDIM];
__device__ float g_kv  [NBH * EDIM * EDIM];
__device__ float g_ksum[NBH * EDIM];
__device__ float g_kvp [KSPLIT * NBH * EDIM * EDIM];
__device__ float g_ksp [KSPLIT * NBH * EDIM];

__device__ __half g_xh [(size_t)TOK * CDIM];
__device__ __half g_xl [(size_t)TOK * CDIM];
__device__ __half g_ah [(size_t)TOK * CDIM];
__device__ __half g_al [(size_t)TOK * CDIM];
__device__ __half g_wqh[(size_t)NQKV * CDIM];
__device__ __half g_wph[(size_t)CDIM * CDIM];

// ---------------- PTX helpers (sm_80-level only; nothing 'a'-gated) --------
__device__ __forceinline__ uint32_t smem_to_u32(const void* p) {
    uint32_t a;
    asm("{ .reg .u64 t; cvta.to.shared.u64 t, %1; cvt.u32.u64 %0, t; }"
        : "=r"(a) : "l"(p));
    return a;
}
__device__ __forceinline__ void cp16(uint32_t saddr, const void* gaddr) {
    asm volatile("cp.async.cg.shared.global [%0], [%1], 16;"
                 :: "r"(saddr), "l"(gaddr) : "memory");
}
#define CP_COMMIT() asm volatile("cp.async.commit_group;" ::: "memory")
#define CP_WAIT2()  asm volatile("cp.async.wait_group 2;" ::: "memory")

__device__ __forceinline__ void ldmx4(uint32_t* r, uint32_t addr) {
    asm volatile("ldmatrix.sync.aligned.m8n8.x4.shared.b16 {%0,%1,%2,%3}, [%4];"
                 : "=r"(r[0]), "=r"(r[1]), "=r"(r[2]), "=r"(r[3]) : "r"(addr));
}
__device__ __forceinline__ void mma_f16(float* c, const uint32_t* a, const uint32_t* b) {
    asm volatile(
        "mma.sync.aligned.m16n8k16.row.col.f32.f16.f16.f32 "
        "{%0,%1,%2,%3}, {%4,%5,%6,%7}, {%8,%9}, {%0,%1,%2,%3};"
        : "+f"(c[0]), "+f"(c[1]), "+f"(c[2]), "+f"(c[3])
        : "r"(a[0]), "r"(a[1]), "r"(a[2]), "r"(a[3]), "r"(b[0]), "r"(b[1]));
}

// ---------------- GEMM tiling: CTA 128x256, 512 thr, warp tile 32x64 -------
#define LDS_T   40                     // fp16 per smem row (32 + 8 pad)
#define TILE_A  (128 * LDS_T * 2)      // 10240 B
#define TILE_BN (256 * LDS_T * 2)      // 20480 B
#define OFF_AH  0
#define OFF_AL  TILE_A
#define OFF_B   (2 * TILE_A)
#define STAGE_B (2 * TILE_A + TILE_BN) // 40960
#define STAGES  4
#define GEMM_SMEM (STAGES * STAGE_B)   // 163840 (1 CTA/SM)
#define KTILES  (CDIM / 32)            // 24
#define NTHREADS 512

// ---------------------------------------------------------------------------
// split fp32 -> (fp16 hi, fp16 lo)
// ---------------------------------------------------------------------------
__global__ void split_f16(const float* __restrict__ src,
                          __half* __restrict__ hi,
                          __half* __restrict__ lo, int n4)
{
    int i = blockIdx.x * blockDim.x + threadIdx.x;
    if (i >= n4) return;
    float4 v = ((const float4*)src)[i];
    __half h0 = __float2half_rn(v.x);
    __half h1 = __float2half_rn(v.y);
    __half h2 = __float2half_rn(v.z);
    __half h3 = __float2half_rn(v.w);
    __half2* H = (__half2*)hi;
    __half2* L = (__half2*)lo;
    H[2 * i + 0] = __halves2half2(h0, h1);
    H[2 * i + 1] = __halves2half2(h2, h3);
    L[2 * i + 0] = __halves2half2(__float2half_rn(v.x - __half2float(h0)),
                                  __float2half_rn(v.y - __half2float(h1)));
    L[2 * i + 1] = __halves2half2(__float2half_rn(v.z - __half2float(h2)),
                                  __float2half_rn(v.w - __half2float(h3)));
}

// round fp32 -> fp16 (weights: hi only)
__global__ void round_f16(const float* __restrict__ src,
                          __half* __restrict__ hi, int n4)
{
    int i = blockIdx.x * blockDim.x + threadIdx.x;
    if (i >= n4) return;
    float4 v = ((const float4*)src)[i];
    __half2* H = (__half2*)hi;
    H[2 * i + 0] = __halves2half2(__float2half_rn(v.x), __float2half_rn(v.y));
    H[2 * i + 1] = __halves2half2(__float2half_rn(v.z), __float2half_rn(v.w));
}

// ---------------------------------------------------------------------------
// mma.sync TN GEMM, fp16 2-pass split: C[m,n] = sum_k (Ah+Al)[m,k]*Bh[n,k].
// CTA tile 128x256, BK=32, 512 threads (16 warps, 4 m x 4 n), warp tile
// 32x64, cp.async 4-stage pipeline, 1 CTA/SM.
// mode 0: qkv epilogue; mode 1: proj epilogue.
// ---------------------------------------------------------------------------
__global__ __launch_bounds__(NTHREADS, 1) void gemm_mma(
    const __half* __restrict__ Ah, const __half* __restrict__ Al,
    const __half* __restrict__ Bh,
    const float* __restrict__ bias, float* __restrict__ Cout, int mode)
{
    extern __shared__ char smem[];
    const uint32_t sb  = smem_to_u32(smem);
    const int tid  = threadIdx.x;
    const int lane = tid & 31, wid = tid >> 5;
    const int bx = blockIdx.x, by = blockIdx.y;

    const int warp_m = wid & 3, warp_n = wid >> 2;   // 4 x 4 warp grid
    const int m0 = warp_m * 32, n0 = warp_n * 64;

    // per-lane ldmatrix byte offsets (within a stage)
    const uint32_t a_off = (uint32_t)((m0 + (lane & 15)) * LDS_T + (lane >> 4) * 8) * 2;
    const uint32_t b_off = (uint32_t)((n0 + (lane & 7) + ((lane >> 4) << 3)) * LDS_T
                                      + ((lane >> 3) & 1) * 8) * 2;

    float acc[2][8][4];
    #pragma unroll
    for (int i = 0; i < 2; i++)
        #pragma unroll
        for (int j = 0; j < 8; j++)
            #pragma unroll
            for (int c = 0; c < 4; c++) acc[i][j][c] = 0.0f;

    // cp.async mapping: 2048 x 16B chunks per stage, 4 per thread.
    // A (hi,lo): 128 rows x 4 chunks; B: 256 rows x 4 chunks.
    const int a_row = tid >> 2, a_cc = tid & 3;              // A chunk = tid
    const int b_row0 = a_row, b_cc = a_cc;                   // B chunks = tid, tid+512

    auto load_stage = [&](int stage, int kt) {
        const uint32_t s0 = sb + stage * STAGE_B;
        const int k0 = kt * 32;
        const uint32_t soA = (uint32_t)(a_row * LDS_T + a_cc * 8) * 2;
        const size_t goA = (size_t)(by * 128 + a_row) * CDIM + k0 + a_cc * 8;
        cp16(s0 + OFF_AH + soA, Ah + goA);
        cp16(s0 + OFF_AL + soA, Al + goA);
        #pragma unroll
        for (int i = 0; i < 2; i++) {
            const int br = b_row0 + i * 128;
            const uint32_t soB = (uint32_t)(br * LDS_T + b_cc * 8) * 2;
            const size_t goB = (size_t)(bx * 256 + br) * CDIM + k0 + b_cc * 8;
            cp16(s0 + OFF_B + soB, Bh + goB);
        }
        CP_COMMIT();
    };

    auto compute_stage = [&](int stage) {
        const uint32_t s0 = sb + stage * STAGE_B;
        #pragma unroll
        for (int ks = 0; ks < 2; ks++) {
            const uint32_t kb = (uint32_t)(ks * 16) * 2;
            uint32_t ah[2][4], bh[4][4];
            #pragma unroll
            for (int am = 0; am < 2; am++)
                ldmx4(ah[am], s0 + OFF_AH + a_off + kb + (uint32_t)(am * 16 * LDS_T) * 2);
            #pragma unroll
            for (int p = 0; p < 4; p++)
                ldmx4(bh[p], s0 + OFF_B + b_off + kb + (uint32_t)(p * 16 * LDS_T) * 2);
            #pragma unroll
            for (int am = 0; am < 2; am++)
                #pragma unroll
                for (int bn = 0; bn < 8; bn++)
                    mma_f16(acc[am][bn], ah[am], &bh[bn >> 1][(bn & 1) * 2]);

            uint32_t al[2][4];
            #pragma unroll
            for (int am = 0; am < 2; am++)
                ldmx4(al[am], s0 + OFF_AL + a_off + kb + (uint32_t)(am * 16 * LDS_T) * 2);
            #pragma unroll
            for (int am = 0; am < 2; am++)
                #pragma unroll
                for (int bn = 0; bn < 8; bn++)
                    mma_f16(acc[am][bn], al[am], &bh[bn >> 1][(bn & 1) * 2]);
        }
    };

    load_stage(0, 0);
    load_stage(1, 1);
    load_stage(2, 2);
    int buf = 0;
    for (int kt = 0; kt < KTILES; kt++) {
        CP_WAIT2();                      // group kt complete (<=2 pending)
        __syncthreads();
        if (kt + 3 < KTILES) load_stage((kt + 3) & 3, kt + 3);
        compute_stage(buf);
        buf = (buf + 1) & 3;
    }

    // ---------------- epilogue: direct register -> gmem (float2 stores) -----
    const int rbase = by * 128 + m0;
    const int crow  = lane >> 2;          // 0..7
    const int ccol  = (lane & 3) * 2;

    if (mode == 0) {
        const int which = (bx * 256) / CDIM;          // 0:q 1:k 2:v (256 | 768 tiles)
        float* dst = (which == 0) ? g_q : (which == 1) ? g_k : g_v;
        const bool rl = (which < 2);
        const int cbase = bx * 256 - which * CDIM + n0;
        #pragma unroll
        for (int am = 0; am < 2; am++) {
            #pragma unroll
            for (int bn = 0; bn < 8; bn++) {
                const int row = rbase + am * 16 + crow;
                const int col = cbase + bn * 8 + ccol;
                float2 v0 = make_float2(acc[am][bn][0], acc[am][bn][1]);
                float2 v1 = make_float2(acc[am][bn][2], acc[am][bn][3]);
                if (rl) {
                    v0.x = fmaxf(v0.x, 0.f); v0.y = fmaxf(v0.y, 0.f);
                    v1.x = fmaxf(v1.x, 0.f); v1.y = fmaxf(v1.y, 0.f);
                }
                *(float2*)(dst + (size_t)row * CDIM + col)       = v0;
                *(float2*)(dst + (size_t)(row + 8) * CDIM + col) = v1;
            }
        }
    } else {
        const int cbase = bx * 256 + n0;
        #pragma unroll
        for (int am = 0; am < 2; am++) {
            #pragma unroll
            for (int bn = 0; bn < 8; bn++) {
                const int row = rbase + am * 16 + crow;
                const int col = cbase + bn * 8 + ccol;
                const float b0 = bias[col], b1 = bias[col + 1];
                float2 v0 = make_float2(acc[am][bn][0] + b0, acc[am][bn][1] + b1);
                float2 v1 = make_float2(acc[am][bn][2] + b0, acc[am][bn][3] + b1);
                *(float2*)(Cout + (size_t)row * CDIM + col)       = v0;
                *(float2*)(Cout + (size_t)(row + 8) * CDIM + col) = v1;
            }
        }
    }
}

// ---------------------------------------------------------------------------
// kv partial: per (bh, s-split) accumulate kv outer products + ksum
// ---------------------------------------------------------------------------
__global__ __launch_bounds__(256) void kv_partial()
{
    const int bh = blockIdx.x;          // 0..95
    const int sp = blockIdx.y;          // 0..6
    const int b  = bh / HEADS;
    const int h  = bh % HEADS;
    const float* kbase = g_k + (size_t)b * SDIM * CDIM + h * EDIM;
    const float* vbase = g_v + (size_t)b * SDIM * CDIM + h * EDIM;

    __shared__ float ks[8][EDIM];
    __shared__ float vs[8][EDIM];

    const int tid = threadIdx.x;
    const int tx  = tid & 15, ty = tid >> 4;

    float acc[4][4];
    #pragma unroll
    for (int i = 0; i < 4; i++)
        #pragma unroll
        for (int j = 0; j < 4; j++) acc[i][j] = 0.0f;
    float ksum = 0.0f;

    const int s_beg = sp * SCHUNK, s_end = s_beg + SCHUNK;
    for (int s0 = s_beg; s0 < s_end; s0 += 8) {
        for (int i = tid; i < 8 * EDIM; i += 256) {
            const int sr = i >> 6, e = i & 63;
            ks[sr][e] = kbase[(size_t)(s0 + sr) * CDIM + e];
            vs[sr][e] = vbase[(size_t)(s0 + sr) * CDIM + e];
        }
        __syncthreads();
        #pragma unroll
        for (int sr = 0; sr < 8; sr++) {
            float rk[4], rv[4];
            #pragma unroll
            for (int i = 0; i < 4; i++) rk[i] = ks[sr][ty * 4 + i];
            #pragma unroll
            for (int j = 0; j < 4; j++) rv[j] = vs[sr][tx * 4 + j];
            #pragma unroll
            for (int i = 0; i < 4; i++)
                #pragma unroll
                for (int j = 0; j < 4; j++)
                    acc[i][j] = fmaf(rk[i], rv[j], acc[i][j]);
            if (tid < EDIM) ksum += ks[sr][tid];
        }
        __syncthreads();
    }

    float* kvout = g_kvp + ((size_t)sp * NBH + bh) * EDIM * EDIM;
    #pragma unroll
    for (int i = 0; i < 4; i++)
        #pragma unroll
        for (int j = 0; j < 4; j++)
            kvout[(ty * 4 + i) * EDIM + tx * 4 + j] = acc[i][j];
    if (tid < EDIM) g_ksp[((size_t)sp * NBH + bh) * EDIM + tid] = ksum;
}

__global__ __launch_bounds__(256) void kv_final()
{
    const int bh = blockIdx.x;
    const int tid = threadIdx.x;
    for (int i = tid; i < EDIM * EDIM; i += 256) {
        float s = 0.0f;
        #pragma unroll
        for (int sp = 0; sp < KSPLIT; sp++)
            s += g_kvp[((size_t)sp * NBH + bh) * EDIM * EDIM + i];
        g_kv[(size_t)bh * EDIM * EDIM + i] = s;
    }
    if (tid < EDIM) {
        float s = 0.0f;
        #pragma unroll
        for (int sp = 0; sp < KSPLIT; sp++)
            s += g_ksp[((size_t)sp * NBH + bh) * EDIM + tid];
        g_ksum[bh * EDIM + tid] = s;
    }
}

// ---------------------------------------------------------------------------
// attention output: out = (q @ kv) * z  -> written directly as fp16 hi/lo
// ---------------------------------------------------------------------------
__global__ __launch_bounds__(256) void attn_out()
{
    const int bh = blockIdx.x;
    const int st = blockIdx.y;
    const int b  = bh / HEADS;
    const int h  = bh % HEADS;

    __shared__ float kvs[EDIM][EDIM + 1];
    __shared__ float qs [EDIM][EDIM + 1];
    __shared__ float ksum_s[EDIM];
    __shared__ float zs[EDIM];

    const int tid = threadIdx.x;
    const int tx  = tid & 15, ty = tid >> 4;

    const float* qbase  = g_q + (size_t)(b * SDIM + st * 64) * CDIM + h * EDIM;
    const float* kvbase = g_kv + (size_t)bh * EDIM * EDIM;

    for (int i = tid; i < EDIM * EDIM; i += 256) {
        const int r = i >> 6, c = i & 63;
        kvs[r][c] = kvbase[i];
        qs [r][c] = qbase[(size_t)r * CDIM + c];
    }
    if (tid < EDIM) ksum_s[tid] = g_ksum[bh * EDIM + tid];
    __syncthreads();

    if (tid < EDIM) {
        float d = 0.0f;
        #pragma unroll
        for (int e = 0; e < EDIM; e++) d = fmaf(qs[tid][e], ksum_s[e], d);
        zs[tid] = 1.0f / (d + EPSV);
    }
    __syncthreads();

    float acc[4][4];
    #pragma unroll
    for (int i = 0; i < 4; i++)
        #pragma unroll
        for (int j = 0; j < 4; j++) acc[i][j] = 0.0f;

    #pragma unroll 8
    for (int e = 0; e < EDIM; e++) {
        float rq[4], rkv[4];
        #pragma unroll
        for (int i = 0; i < 4; i++) rq[i] = qs[ty * 4 + i][e];
        #pragma unroll
        for (int j = 0; j < 4; j++) rkv[j] = kvs[e][tx * 4 + j];
        #pragma unroll
        for (int i = 0; i < 4; i++)
            #pragma unroll
            for (int j = 0; j < 4; j++)
                acc[i][j] = fmaf(rq[i], rkv[j], acc[i][j]);
    }

    #pragma unroll
    for (int i = 0; i < 4; i++) {
        const int s = ty * 4 + i;
        const size_t token = (size_t)(b * SDIM + st * 64 + s);
        const float z = zs[s];
        __half2* hrow = (__half2*)(g_ah + token * CDIM + h * EDIM + tx * 4);
        __half2* lrow = (__half2*)(g_al + token * CDIM + h * EDIM + tx * 4);
        #pragma unroll
        for (int j2 = 0; j2 < 2; j2++) {
            float f0 = acc[i][j2 * 2 + 0] * z;
            float f1 = acc[i][j2 * 2 + 1] * z;
            __half h0 = __float2half_rn(f0);
            __half h1 = __float2half_rn(f1);
            hrow[j2] = __halves2half2(h0, h1);
            lrow[j2] = __halves2half2(__float2half_rn(f0 - __half2float(h0)),
                                      __float2half_rn(f1 - __half2float(h1)));
        }
    }
}

// ---------------------------------------------------------------------------
extern "C" void kernel_launch(void* const* d_in, const int* in_sizes, int n_in,
                              void* d_out, int out_size)
{
    const float* x     = (const float*)d_in[0];
    const float* Wqkv  = (const float*)d_in[1];
    const float* Wproj = (const float*)d_in[2];
    const float* bproj = (const float*)d_in[3];
    float* out = (float*)d_out;

    static int init_done = 0;
    if (!init_done) {
        cudaFuncSetAttribute(gemm_mma,
                             cudaFuncAttributeMaxDynamicSharedMemorySize, GEMM_SMEM);
        init_done = 1;
    }

    __half *xh, *xl, *ah, *al, *wqh, *wph;
    cudaGetSymbolAddress((void**)&xh,  g_xh);
    cudaGetSymbolAddress((void**)&xl,  g_xl);
    cudaGetSymbolAddress((void**)&ah,  g_ah);
    cudaGetSymbolAddress((void**)&al,  g_al);
    cudaGetSymbolAddress((void**)&wqh, g_wqh);
    cudaGetSymbolAddress((void**)&wph, g_wph);

    // 1) fp32 -> fp16 splits (x: hi+lo; weights: hi only)
    {
        int n4 = (TOK * CDIM) / 4;
        split_f16<<<(n4 + 255) / 256, 256>>>(x, xh, xl, n4);
        n4 = (NQKV * CDIM) / 4;
        round_f16<<<(n4 + 255) / 256, 256>>>(Wqkv, wqh, n4);
        n4 = (CDIM * CDIM) / 4;
        round_f16<<<(n4 + 255) / 256, 256>>>(Wproj, wph, n4);
    }
    // 2) qkv GEMM (tensor core mma.sync, fp16 2-pass) -> g_q/g_k/g_v
    gemm_mma<<<dim3(NQKV / 256, TOK / 128), NTHREADS, GEMM_SMEM>>>(
        xh, xl, wqh, nullptr, nullptr, 0);
    // 3) kv reduction (split over S) + combine
    kv_partial<<<dim3(NBH, KSPLIT), 256>>>();
    kv_final<<<NBH, 256>>>();
    // 4) attention output -> g_ah/g_al (fused fp16 split)
    attn_out<<<dim3(NBH, SDIM / 64), 256>>>();
    // 5) proj GEMM -> out
    gemm_mma<<<dim3(CDIM / 256, TOK / 128), NTHREADS, GEMM_SMEM>>>(
        ah, al, wph, bproj, out, 1);
}

// round 17
// speedup vs baseline: 4.3925x; 1.0667x over previous
#include <cuda_runtime.h>
#include <cuda_fp16.h>
#include <cstdint>

// ---------------- problem constants ----------------
#define TOK   25088      // B*N
#define CDIM  768
#define NQKV  2304
#define HEADS 12
#define EDIM  64
#define NBH   96
#define SDIM  3136
#define EPSV  1e-4f
#define KSPLIT 7
#define SCHUNK (SDIM / KSPLIT)   // 448

// ---------------- scratch (__device__ globals; no allocs allowed) ----------
__device__ float g_q   [(size_t)TOK * CDIM];
__device__ float g_k   [(size_t)TOK * CDIM];
__device__ float g_v   [(size_t)TOK * CDIM];
__device__ float g_kv  [NBH * EDIM * EDIM];
__device__ float g_ksum[NBH * EDIM];
__device__ float g_kvp [KSPLIT * NBH * EDIM * EDIM];
__device__ float g_ksp [KSPLIT * NBH * EDIM];

__device__ __half g_xh [(size_t)TOK * CDIM];
__device__ __half g_xl [(size_t)TOK * CDIM];
__device__ __half g_ah [(size_t)TOK * CDIM];
__device__ __half g_wqh[(size_t)NQKV * CDIM];
__device__ __half g_wph[(size_t)CDIM * CDIM];

// ---------------- PTX helpers (sm_80-level only; nothing 'a'-gated) --------
__device__ __forceinline__ uint32_t smem_to_u32(const void* p) {
    uint32_t a;
    asm("{ .reg .u64 t; cvta.to.shared.u64 t, %1; cvt.u32.u64 %0, t; }"
        : "=r"(a) : "l"(p));
    return a;
}
__device__ __forceinline__ void cp16(uint32_t saddr, const void* gaddr) {
    asm volatile("cp.async.cg.shared.global [%0], [%1], 16;"
                 :: "r"(saddr), "l"(gaddr) : "memory");
}
#define CP_COMMIT() asm volatile("cp.async.commit_group;" ::: "memory")
#define CP_WAIT2()  asm volatile("cp.async.wait_group 2;" ::: "memory")

__device__ __forceinline__ void ldmx4(uint32_t* r, uint32_t addr) {
    asm volatile("ldmatrix.sync.aligned.m8n8.x4.shared.b16 {%0,%1,%2,%3}, [%4];"
                 : "=r"(r[0]), "=r"(r[1]), "=r"(r[2]), "=r"(r[3]) : "r"(addr));
}
__device__ __forceinline__ void mma_f16(float* c, const uint32_t* a, const uint32_t* b) {
    asm volatile(
        "mma.sync.aligned.m16n8k16.row.col.f32.f16.f16.f32 "
        "{%0,%1,%2,%3}, {%4,%5,%6,%7}, {%8,%9}, {%0,%1,%2,%3};"
        : "+f"(c[0]), "+f"(c[1]), "+f"(c[2]), "+f"(c[3])
        : "r"(a[0]), "r"(a[1]), "r"(a[2]), "r"(a[3]), "r"(b[0]), "r"(b[1]));
}

// ---------------- GEMM tiling: CTA 128x256, 512 thr, warp tile 32x64 -------
#define LDS_T   40                     // fp16 per smem row (32 + 8 pad)
#define TILE_A  (128 * LDS_T * 2)      // 10240 B
#define TILE_BN (256 * LDS_T * 2)      // 20480 B
#define OFF_AH  0
#define OFF_AL  TILE_A
#define OFF_B   (2 * TILE_A)
#define STAGE_B (2 * TILE_A + TILE_BN) // 40960
#define STAGES  4
#define GEMM_SMEM (STAGES * STAGE_B)   // 163840 (1 CTA/SM)
#define KTILES  (CDIM / 32)            // 24
#define NTHREADS 512

// ---------------------------------------------------------------------------
// split fp32 -> (fp16 hi, fp16 lo)
// ---------------------------------------------------------------------------
__global__ void split_f16(const float* __restrict__ src,
                          __half* __restrict__ hi,
                          __half* __restrict__ lo, int n4)
{
    int i = blockIdx.x * blockDim.x + threadIdx.x;
    if (i >= n4) return;
    float4 v = ((const float4*)src)[i];
    __half h0 = __float2half_rn(v.x);
    __half h1 = __float2half_rn(v.y);
    __half h2 = __float2half_rn(v.z);
    __half h3 = __float2half_rn(v.w);
    __half2* H = (__half2*)hi;
    __half2* L = (__half2*)lo;
    H[2 * i + 0] = __halves2half2(h0, h1);
    H[2 * i + 1] = __halves2half2(h2, h3);
    L[2 * i + 0] = __halves2half2(__float2half_rn(v.x - __half2float(h0)),
                                  __float2half_rn(v.y - __half2float(h1)));
    L[2 * i + 1] = __halves2half2(__float2half_rn(v.z - __half2float(h2)),
                                  __float2half_rn(v.w - __half2float(h3)));
}

// round fp32 -> fp16 (weights: hi only)
__global__ void round_f16(const float* __restrict__ src,
                          __half* __restrict__ hi, int n4)
{
    int i = blockIdx.x * blockDim.x + threadIdx.x;
    if (i >= n4) return;
    float4 v = ((const float4*)src)[i];
    __half2* H = (__half2*)hi;
    H[2 * i + 0] = __halves2half2(__float2half_rn(v.x), __float2half_rn(v.y));
    H[2 * i + 1] = __halves2half2(__float2half_rn(v.z), __float2half_rn(v.w));
}

// ---------------------------------------------------------------------------
// mma.sync TN GEMM. QKV=1: 2-pass fp16 split (C = (Ah+Al)*Bh), epilogue
// splits into g_q/g_k/g_v with relu. QKV=0: 1-pass (C = Ah*Bh), bias add.
// CTA tile 128x256, BK=32, 512 threads (16 warps, 4 m x 4 n), warp tile
// 32x64, cp.async 4-stage pipeline, 1 CTA/SM.
// ---------------------------------------------------------------------------
template<int QKV>
__global__ __launch_bounds__(NTHREADS, 1) void gemm_mma(
    const __half* __restrict__ Ah, const __half* __restrict__ Al,
    const __half* __restrict__ Bh,
    const float* __restrict__ bias, float* __restrict__ Cout)
{
    extern __shared__ char smem[];
    const uint32_t sb  = smem_to_u32(smem);
    const int tid  = threadIdx.x;
    const int lane = tid & 31, wid = tid >> 5;
    const int bx = blockIdx.x, by = blockIdx.y;

    const int warp_m = wid & 3, warp_n = wid >> 2;   // 4 x 4 warp grid
    const int m0 = warp_m * 32, n0 = warp_n * 64;

    // per-lane ldmatrix byte offsets (within a stage)
    const uint32_t a_off = (uint32_t)((m0 + (lane & 15)) * LDS_T + (lane >> 4) * 8) * 2;
    const uint32_t b_off = (uint32_t)((n0 + (lane & 7) + ((lane >> 4) << 3)) * LDS_T
                                      + ((lane >> 3) & 1) * 8) * 2;

    float acc[2][8][4];
    #pragma unroll
    for (int i = 0; i < 2; i++)
        #pragma unroll
        for (int j = 0; j < 8; j++)
            #pragma unroll
            for (int c = 0; c < 4; c++) acc[i][j][c] = 0.0f;

    const int a_row = tid >> 2, a_cc = tid & 3;

    auto load_stage = [&](int stage, int kt) {
        const uint32_t s0 = sb + stage * STAGE_B;
        const int k0 = kt * 32;
        const uint32_t soA = (uint32_t)(a_row * LDS_T + a_cc * 8) * 2;
        const size_t goA = (size_t)(by * 128 + a_row) * CDIM + k0 + a_cc * 8;
        cp16(s0 + OFF_AH + soA, Ah + goA);
        if (QKV) cp16(s0 + OFF_AL + soA, Al + goA);
        #pragma unroll
        for (int i = 0; i < 2; i++) {
            const int br = a_row + i * 128;
            const uint32_t soB = (uint32_t)(br * LDS_T + a_cc * 8) * 2;
            const size_t goB = (size_t)(bx * 256 + br) * CDIM + k0 + a_cc * 8;
            cp16(s0 + OFF_B + soB, Bh + goB);
        }
        CP_COMMIT();
    };

    auto compute_stage = [&](int stage) {
        const uint32_t s0 = sb + stage * STAGE_B;
        #pragma unroll
        for (int ks = 0; ks < 2; ks++) {
            const uint32_t kb = (uint32_t)(ks * 16) * 2;
            uint32_t ah[2][4], bh[4][4], al[2][4];
            #pragma unroll
            for (int am = 0; am < 2; am++)
                ldmx4(ah[am], s0 + OFF_AH + a_off + kb + (uint32_t)(am * 16 * LDS_T) * 2);
            #pragma unroll
            for (int p = 0; p < 4; p++)
                ldmx4(bh[p], s0 + OFF_B + b_off + kb + (uint32_t)(p * 16 * LDS_T) * 2);
            if (QKV) {
                // issue lo-A loads now; latency hidden under hi-pass MMAs
                #pragma unroll
                for (int am = 0; am < 2; am++)
                    ldmx4(al[am], s0 + OFF_AL + a_off + kb + (uint32_t)(am * 16 * LDS_T) * 2);
            }
            #pragma unroll
            for (int am = 0; am < 2; am++)
                #pragma unroll
                for (int bn = 0; bn < 8; bn++)
                    mma_f16(acc[am][bn], ah[am], &bh[bn >> 1][(bn & 1) * 2]);
            if (QKV) {
                #pragma unroll
                for (int am = 0; am < 2; am++)
                    #pragma unroll
                    for (int bn = 0; bn < 8; bn++)
                        mma_f16(acc[am][bn], al[am], &bh[bn >> 1][(bn & 1) * 2]);
            }
        }
    };

    load_stage(0, 0);
    load_stage(1, 1);
    load_stage(2, 2);
    int buf = 0;
    for (int kt = 0; kt < KTILES; kt++) {
        CP_WAIT2();
        __syncthreads();
        if (kt + 3 < KTILES) load_stage((kt + 3) & 3, kt + 3);
        compute_stage(buf);
        buf = (buf + 1) & 3;
    }

    // ---------------- epilogue: direct register -> gmem (float2 stores) -----
    const int rbase = by * 128 + m0;
    const int crow  = lane >> 2;
    const int ccol  = (lane & 3) * 2;

    if (QKV) {
        const int which = (bx * 256) / CDIM;          // 0:q 1:k 2:v
        float* dst = (which == 0) ? g_q : (which == 1) ? g_k : g_v;
        const bool rl = (which < 2);
        const int cbase = bx * 256 - which * CDIM + n0;
        #pragma unroll
        for (int am = 0; am < 2; am++) {
            #pragma unroll
            for (int bn = 0; bn < 8; bn++) {
                const int row = rbase + am * 16 + crow;
                const int col = cbase + bn * 8 + ccol;
                float2 v0 = make_float2(acc[am][bn][0], acc[am][bn][1]);
                float2 v1 = make_float2(acc[am][bn][2], acc[am][bn][3]);
                if (rl) {
                    v0.x = fmaxf(v0.x, 0.f); v0.y = fmaxf(v0.y, 0.f);
                    v1.x = fmaxf(v1.x, 0.f); v1.y = fmaxf(v1.y, 0.f);
                }
                *(float2*)(dst + (size_t)row * CDIM + col)       = v0;
                *(float2*)(dst + (size_t)(row + 8) * CDIM + col) = v1;
            }
        }
    } else {
        const int cbase = bx * 256 + n0;
        #pragma unroll
        for (int am = 0; am < 2; am++) {
            #pragma unroll
            for (int bn = 0; bn < 8; bn++) {
                const int row = rbase + am * 16 + crow;
                const int col = cbase + bn * 8 + ccol;
                const float b0 = bias[col], b1 = bias[col + 1];
                float2 v0 = make_float2(acc[am][bn][0] + b0, acc[am][bn][1] + b1);
                float2 v1 = make_float2(acc[am][bn][2] + b0, acc[am][bn][3] + b1);
                *(float2*)(Cout + (size_t)row * CDIM + col)       = v0;
                *(float2*)(Cout + (size_t)(row + 8) * CDIM + col) = v1;
            }
        }
    }
}

// ---------------------------------------------------------------------------
// kv partial: per (bh, s-split) accumulate kv outer products + ksum
// ---------------------------------------------------------------------------
__global__ __launch_bounds__(256) void kv_partial()
{
    const int bh = blockIdx.x;          // 0..95
    const int sp = blockIdx.y;          // 0..6
    const int b  = bh / HEADS;
    const int h  = bh % HEADS;
    const float* kbase = g_k + (size_t)b * SDIM * CDIM + h * EDIM;
    const float* vbase = g_v + (size_t)b * SDIM * CDIM + h * EDIM;

    __shared__ float ks[8][EDIM];
    __shared__ float vs[8][EDIM];

    const int tid = threadIdx.x;
    const int tx  = tid & 15, ty = tid >> 4;

    float acc[4][4];
    #pragma unroll
    for (int i = 0; i < 4; i++)
        #pragma unroll
        for (int j = 0; j < 4; j++) acc[i][j] = 0.0f;
    float ksum = 0.0f;

    const int s_beg = sp * SCHUNK, s_end = s_beg + SCHUNK;
    for (int s0 = s_beg; s0 < s_end; s0 += 8) {
        for (int i = tid; i < 8 * EDIM; i += 256) {
            const int sr = i >> 6, e = i & 63;
            ks[sr][e] = kbase[(size_t)(s0 + sr) * CDIM + e];
            vs[sr][e] = vbase[(size_t)(s0 + sr) * CDIM + e];
        }
        __syncthreads();
        #pragma unroll
        for (int sr = 0; sr < 8; sr++) {
            float rk[4], rv[4];
            #pragma unroll
            for (int i = 0; i < 4; i++) rk[i] = ks[sr][ty * 4 + i];
            #pragma unroll
            for (int j = 0; j < 4; j++) rv[j] = vs[sr][tx * 4 + j];
            #pragma unroll
            for (int i = 0; i < 4; i++)
                #pragma unroll
                for (int j = 0; j < 4; j++)
                    acc[i][j] = fmaf(rk[i], rv[j], acc[i][j]);
            if (tid < EDIM) ksum += ks[sr][tid];
        }
        __syncthreads();
    }

    float* kvout = g_kvp + ((size_t)sp * NBH + bh) * EDIM * EDIM;
    #pragma unroll
    for (int i = 0; i < 4; i++)
        #pragma unroll
        for (int j = 0; j < 4; j++)
            kvout[(ty * 4 + i) * EDIM + tx * 4 + j] = acc[i][j];
    if (tid < EDIM) g_ksp[((size_t)sp * NBH + bh) * EDIM + tid] = ksum;
}

__global__ __launch_bounds__(256) void kv_final()
{
    const int bh = blockIdx.x;
    const int tid = threadIdx.x;
    for (int i = tid; i < EDIM * EDIM; i += 256) {
        float s = 0.0f;
        #pragma unroll
        for (int sp = 0; sp < KSPLIT; sp++)
            s += g_kvp[((size_t)sp * NBH + bh) * EDIM * EDIM + i];
        g_kv[(size_t)bh * EDIM * EDIM + i] = s;
    }
    if (tid < EDIM) {
        float s = 0.0f;
        #pragma unroll
        for (int sp = 0; sp < KSPLIT; sp++)
            s += g_ksp[((size_t)sp * NBH + bh) * EDIM + tid];
        g_ksum[bh * EDIM + tid] = s;
    }
}

// ---------------------------------------------------------------------------
// attention output: out = (q @ kv) * z  -> fp16 (hi only; proj is 1-pass)
// ---------------------------------------------------------------------------
__global__ __launch_bounds__(256) void attn_out()
{
    const int bh = blockIdx.x;
    const int st = blockIdx.y;
    const int b  = bh / HEADS;
    const int h  = bh % HEADS;

    __shared__ float kvs[EDIM][EDIM + 1];
    __shared__ float qs [EDIM][EDIM + 1];
    __shared__ float ksum_s[EDIM];
    __shared__ float zs[EDIM];

    const int tid = threadIdx.x;
    const int tx  = tid & 15, ty = tid >> 4;

    const float* qbase  = g_q + (size_t)(b * SDIM + st * 64) * CDIM + h * EDIM;
    const float* kvbase = g_kv + (size_t)bh * EDIM * EDIM;

    for (int i = tid; i < EDIM * EDIM; i += 256) {
        const int r = i >> 6, c = i & 63;
        kvs[r][c] = kvbase[i];
        qs [r][c] = qbase[(size_t)r * CDIM + c];
    }
    if (tid < EDIM) ksum_s[tid] = g_ksum[bh * EDIM + tid];
    __syncthreads();

    if (tid < EDIM) {
        float d = 0.0f;
        #pragma unroll
        for (int e = 0; e < EDIM; e++) d = fmaf(qs[tid][e], ksum_s[e], d);
        zs[tid] = 1.0f / (d + EPSV);
    }
    __syncthreads();

    float acc[4][4];
    #pragma unroll
    for (int i = 0; i < 4; i++)
        #pragma unroll
        for (int j = 0; j < 4; j++) acc[i][j] = 0.0f;

    #pragma unroll 8
    for (int e = 0; e < EDIM; e++) {
        float rq[4], rkv[4];
        #pragma unroll
        for (int i = 0; i < 4; i++) rq[i] = qs[ty * 4 + i][e];
        #pragma unroll
        for (int j = 0; j < 4; j++) rkv[j] = kvs[e][tx * 4 + j];
        #pragma unroll
        for (int i = 0; i < 4; i++)
            #pragma unroll
            for (int j = 0; j < 4; j++)
                acc[i][j] = fmaf(rq[i], rkv[j], acc[i][j]);
    }

    #pragma unroll
    for (int i = 0; i < 4; i++) {
        const int s = ty * 4 + i;
        const size_t token = (size_t)(b * SDIM + st * 64 + s);
        const float z = zs[s];
        __half2* hrow = (__half2*)(g_ah + token * CDIM + h * EDIM + tx * 4);
        #pragma unroll
        for (int j2 = 0; j2 < 2; j2++) {
            float f0 = acc[i][j2 * 2 + 0] * z;
            float f1 = acc[i][j2 * 2 + 1] * z;
            hrow[j2] = __halves2half2(__float2half_rn(f0), __float2half_rn(f1));
        }
    }
}

// ---------------------------------------------------------------------------
extern "C" void kernel_launch(void* const* d_in, const int* in_sizes, int n_in,
                              void* d_out, int out_size)
{
    const float* x     = (const float*)d_in[0];
    const float* Wqkv  = (const float*)d_in[1];
    const float* Wproj = (const float*)d_in[2];
    const float* bproj = (const float*)d_in[3];
    float* out = (float*)d_out;

    static int init_done = 0;
    if (!init_done) {
        cudaFuncSetAttribute(gemm_mma<1>,
                             cudaFuncAttributeMaxDynamicSharedMemorySize, GEMM_SMEM);
        cudaFuncSetAttribute(gemm_mma<0>,
                             cudaFuncAttributeMaxDynamicSharedMemorySize, GEMM_SMEM);
        init_done = 1;
    }

    __half *xh, *xl, *ah, *wqh, *wph;
    cudaGetSymbolAddress((void**)&xh,  g_xh);
    cudaGetSymbolAddress((void**)&xl,  g_xl);
    cudaGetSymbolAddress((void**)&ah,  g_ah);
    cudaGetSymbolAddress((void**)&wqh, g_wqh);
    cudaGetSymbolAddress((void**)&wph, g_wph);

    // 1) fp32 -> fp16 splits (x: hi+lo; weights: hi only)
    {
        int n4 = (TOK * CDIM) / 4;
        split_f16<<<(n4 + 255) / 256, 256>>>(x, xh, xl, n4);
        n4 = (NQKV * CDIM) / 4;
        round_f16<<<(n4 + 255) / 256, 256>>>(Wqkv, wqh, n4);
        n4 = (CDIM * CDIM) / 4;
        round_f16<<<(n4 + 255) / 256, 256>>>(Wproj, wph, n4);
    }
    // 2) qkv GEMM (fp16 2-pass) -> g_q/g_k/g_v
    gemm_mma<1><<<dim3(NQKV / 256, TOK / 128), NTHREADS, GEMM_SMEM>>>(
        xh, xl, wqh, nullptr, nullptr);
    // 3) kv reduction (split over S) + combine
    kv_partial<<<dim3(NBH, KSPLIT), 256>>>();
    kv_final<<<NBH, 256>>>();
    // 4) attention output -> g_ah (fp16 hi only)
    attn_out<<<dim3(NBH, SDIM / 64), 256>>>();
    // 5) proj GEMM (fp16 1-pass) -> out
    gemm_mma<0><<<dim3(CDIM / 256, TOK / 128), NTHREADS, GEMM_SMEM>>>(
        ah, nullptr, wph, bproj, out);
}